// round 14
// baseline (speedup 1.0000x reference)
#include <cuda_runtime.h>
#include <cuda_bf16.h>
#include <math.h>

#define NN 20000
#define NE 640000
#define NL 2
#define MAXR 2.5f
#define INV_NN 0.17677669529663687f   // 1/sqrt(32)
#define NPAD 20800                    // attr-sorted node list padded to 8-aligned segments

// ---------------- scratch (device globals; no allocs) ----------------
static __device__ float g_Q[64 * 2];
static __device__ float g_ys[2][NN * 64];
static __device__ float g_yv[2][NN * 192];
static __device__ float g_s1[NN * 64];
static __device__ float g_v1[NN * 192];          // [n][3][64] x-major
static __device__ float g_agg[NN * 256];         // (n, c, 4): vx,vy,vz,s
static __device__ float g_pos[NN * 3];
static __device__ float g_Bs[NL * 100 * 64 * 128];
static __device__ float g_Bv[NL * 100 * 64 * 64];
// edge sort (by dst, filtered); counters zeroed by k_pre of the PREVIOUS call (.bss first)
static __device__ int g_ecnt[NN];
static __device__ int g_eoff[NN];
static __device__ int g_eppos[NN];
static __device__ int g_nesurv;
static __device__ int g_ssrc[NE];
static __device__ int g_sdst[NE];
// node sort (by attr), 8-aligned segments, -1 = sentinel
static __device__ int g_nidx[NPAD];
static __device__ int g_nattr[NPAD];

// ---- fused init: Q + y init + layer0 v1 + B precompute (tiled) + node sort + hist ----
__global__ void __launch_bounds__(256) k_init(const float* __restrict__ x,
                                              const float* __restrict__ M,
                                              const float* __restrict__ emb,
                                              const float* __restrict__ scs,
                                              const float* __restrict__ scv,
                                              const float* __restrict__ lin1v,
                                              const int* __restrict__ attr,
                                              const int* __restrict__ esrc,
                                              const int* __restrict__ edst) {
    int tid = threadIdx.x;
    if (blockIdx.x < 5000) {
        __shared__ double dI[3];
        __shared__ float sQ[128];
        __shared__ float sR[128];
        if (tid < 32) {
            double m0a = M[2 * tid], m1a = M[2 * tid + 1];
            double m0b = M[2 * (tid + 32)], m1b = M[2 * (tid + 32) + 1];
            double pa = m0a * m0a + m0b * m0b;
            double pb = m0a * m1a + m0b * m1b;
            double pc = m1a * m1a + m1b * m1b;
#pragma unroll
            for (int off = 16; off > 0; off >>= 1) {
                pa += __shfl_down_sync(0xffffffffu, pa, off);
                pb += __shfl_down_sync(0xffffffffu, pb, off);
                pc += __shfl_down_sync(0xffffffffu, pc, off);
            }
            if (tid == 0) {
                double det = pa * pc - pb * pb;
                double s = sqrt(det);
                double t = pa + pc;
                double denom = sqrt(t + 2.0 * s);
                double p00 = (pa + s) / denom, p01 = pb / denom, p11 = (pc + s) / denom;
                double pdet = p00 * p11 - p01 * p01;
                dI[0] = p11 / pdet; dI[1] = -p01 / pdet; dI[2] = p00 / pdet;
            }
        }
        __syncthreads();
        if (tid < 64) {
            double m0 = M[2 * tid], m1 = M[2 * tid + 1];
            sQ[2 * tid]     = (float)(m0 * dI[0] + m1 * dI[1]);
            sQ[2 * tid + 1] = (float)(m0 * dI[1] + m1 * dI[2]);
        }
        __syncthreads();
        if (blockIdx.x == 0 && tid < 128) g_Q[tid] = sQ[tid];
        if (tid < 128) {
            int k = tid >> 6, d = tid & 63;
            float acc = 0.f;
#pragma unroll 8
            for (int c = 0; c < 64; c++) acc += sQ[c * 2 + k] * lin1v[c * 64 + d];
            sR[k * 64 + d] = acc;
        }
        __syncthreads();
        int i = blockIdx.x * 256 + tid;
        if (i >= NN * 64) return;
        int n = i >> 6, c = i & 63;
        float q0 = sQ[c * 2], q1 = sQ[c * 2 + 1];
        const float* xp = x + n * 6;
        float v0 = xp[0] * q0 + xp[3] * q1;
        float v1 = xp[1] * q0 + xp[4] * q1;
        float v2 = xp[2] * q0 + xp[5] * q1;
        int base = n * 192 + c * 3;
        g_yv[0][base + 0] = v0; g_yv[0][base + 1] = v1; g_yv[0][base + 2] = v2;
        g_yv[1][base + 0] = v0; g_yv[1][base + 1] = v1; g_yv[1][base + 2] = v2;
        g_ys[0][i] = 0.f; g_ys[1][i] = 0.f;
        if (c < 3) g_pos[n * 3 + c] = xp[c];
        reinterpret_cast<float4*>(g_agg)[i] = make_float4(0.f, 0.f, 0.f, 0.f);
        int d = c;
        float r0 = sR[d], r1 = sR[64 + d];
#pragma unroll
        for (int xx = 0; xx < 3; xx++)
            g_v1[n * 192 + xx * 64 + d] = xp[xx] * r0 + xp[3 + xx] * r1;
    } else if (blockIdx.x < 5256) {
        // ---- B precompute, tiled: one block per (l,c); W column in regs ----
        int b = blockIdx.x - 5000;
        __shared__ __align__(16) float semb[3200];   // 100 x 32 (16B-aligned for LDS.128)
        for (int i = tid; i < 3200; i += 256) semb[i] = emb[i];
        __syncthreads();
        if (b < 128) {
            int l = b >> 6, c = b & 63;
            int o = tid & 127, ah = tid >> 7;       // a-half: 0 -> [0,50), 1 -> [50,100)
            float wcol[32];
            const float* w = scs + ((size_t)(l * 64 + c) * 32) * 128 + o;
#pragma unroll
            for (int e2 = 0; e2 < 32; e2++) wcol[e2] = w[e2 * 128];
            int a0 = ah * 50, a1 = a0 + 50;
            for (int a = a0; a < a1; a++) {
                const float4* em = (const float4*)(semb + a * 32);
                float acc = 0.f;
#pragma unroll
                for (int e4 = 0; e4 < 8; e4++) {
                    float4 u = em[e4];
                    acc += u.x * wcol[e4 * 4] + u.y * wcol[e4 * 4 + 1] +
                           u.z * wcol[e4 * 4 + 2] + u.w * wcol[e4 * 4 + 3];
                }
                g_Bs[((size_t)(l * 100 + a) * 64 + c) * 128 + o] = acc;
            }
        } else {
            int b2 = b - 128;
            int l = b2 >> 6, c = b2 & 63;
            int o = tid & 63, ah = tid >> 6;        // a-quarter: 25 each
            float wcol[32];
            const float* w = scv + ((size_t)(l * 64 + c) * 32) * 64 + o;
#pragma unroll
            for (int e2 = 0; e2 < 32; e2++) wcol[e2] = w[e2 * 64];
            int a0 = ah * 25, a1 = a0 + 25;
            for (int a = a0; a < a1; a++) {
                const float4* em = (const float4*)(semb + a * 32);
                float acc = 0.f;
#pragma unroll
                for (int e4 = 0; e4 < 8; e4++) {
                    float4 u = em[e4];
                    acc += u.x * wcol[e4 * 4] + u.y * wcol[e4 * 4 + 1] +
                           u.z * wcol[e4 * 4 + 2] + u.w * wcol[e4 * 4 + 3];
                }
                g_Bv[((size_t)(l * 100 + a) * 64 + c) * 64 + o] = acc;
            }
        }
    } else if (blockIdx.x == 5256) {
        // single-block node counting sort by attr, segments padded to 8
        __shared__ int scnt[128], soff[128], spos[128];
        if (tid < 128) { scnt[tid] = 0; spos[tid] = 0; }
        __syncthreads();
        for (int n = tid; n < NN; n += 256) atomicAdd(&scnt[attr[n]], 1);
        __syncthreads();
        int pc = 0;
        if (tid < 128) { pc = (scnt[tid] + 7) & ~7; soff[tid] = pc; }
        __syncthreads();
        for (int off = 1; off < 128; off <<= 1) {
            int v = 0;
            if (tid < 128 && tid >= off) v = soff[tid - off];
            __syncthreads();
            if (tid < 128) soff[tid] += v;
            __syncthreads();
        }
        if (tid < 128) soff[tid] -= pc;  // exclusive, 8-aligned
        __syncthreads();
        for (int i = tid; i < NPAD; i += 256) g_nidx[i] = -1;
        __syncthreads();
        for (int n = tid; n < NN; n += 256) {
            int a = attr[n];
            int p = soff[a] + atomicAdd(&spos[a], 1);
            g_nidx[p] = n;
            g_nattr[p] = a;
        }
    } else {
        // FILTERED edge histogram (layer-0 positions = x)
        for (int e = (blockIdx.x - 5257) * 256 + tid; e < NE; e += 1280 * 256) {
            int s = esrc[e], d = edst[e];
            float dx = x[s * 6 + 0] - x[d * 6 + 0];
            float dy = x[s * 6 + 1] - x[d * 6 + 1];
            float dz = x[s * 6 + 2] - x[d * 6 + 2];
            if (dx * dx + dy * dy + dz * dz < MAXR * MAXR)
                atomicAdd(&g_ecnt[d], 1);
        }
    }
}

// ---------------- edge offset scan (writes surviving count) ----------------
__global__ void __launch_bounds__(512) k_scan_e() {
    __shared__ int sp[512];
    int t = threadIdx.x;
    const int CH = 40;
    int base = t * CH;
    int part = 0;
    for (int i = 0; i < CH; i++) {
        int idx = base + i;
        if (idx < NN) part += g_ecnt[idx];
    }
    sp[t] = part;
    __syncthreads();
    for (int off = 1; off < 512; off <<= 1) {
        int v = (t >= off) ? sp[t - off] : 0;
        __syncthreads();
        sp[t] += v;
        __syncthreads();
    }
    if (t == 511) g_nesurv = sp[511];
    int run = sp[t] - part;
    for (int i = 0; i < CH; i++) {
        int idx = base + i;
        if (idx < NN) { g_eoff[idx] = run; run += g_ecnt[idx]; }
    }
}

// ---------------- filtered edge scatter ----------------
__global__ void k_scat_e(const int* __restrict__ esrc, const int* __restrict__ edst,
                         const float* __restrict__ x) {
    for (int e = blockIdx.x * 256 + threadIdx.x; e < NE; e += 1280 * 256) {
        int s = esrc[e], d = edst[e];
        float dx = x[s * 6 + 0] - x[d * 6 + 0];
        float dy = x[s * 6 + 1] - x[d * 6 + 1];
        float dz = x[s * 6 + 2] - x[d * 6 + 2];
        if (dx * dx + dy * dy + dz * dz < MAXR * MAXR) {
            int p = g_eoff[d] + atomicAdd(&g_eppos[d], 1);
            g_ssrc[p] = s;
            g_sdst[p] = d;
        }
    }
}

// ------- pre (layer 1) + sort-counter cleanup for next call's hist -------
__global__ void __launch_bounds__(256) k_pre(const float* __restrict__ lin1s,
                                             const float* __restrict__ lin1v,
                                             int layer, int cur) {
    __shared__ float sWs[4096], sWv[4096];
    __shared__ float sy[8][256];
    int tid = threadIdx.x;
    {
        int i = blockIdx.x * 256 + tid;
        if (i < NN) { g_ecnt[i] = 0; g_eppos[i] = 0; }
    }
    const float* Ws = lin1s + layer * 4096;
    const float* Wv = lin1v + layer * 4096;
    for (int k = tid; k < 4096; k += 256) { sWs[k] = Ws[k]; sWv[k] = Wv[k]; }
    const float* ys = g_ys[cur];
    const float* yv = g_yv[cur];
    int n0 = blockIdx.x * 8;
    for (int k = tid; k < 2048; k += 256) {
        int nn = k >> 8, j = k & 255;
        int n = n0 + nn;
        sy[nn][j] = (j < 64) ? ys[n * 64 + j] : yv[n * 192 + j - 64];
    }
    __syncthreads();
    for (int nn = 0; nn < 8; nn++) {
        int n = n0 + nn;
        if (tid < 64) {
            int d = tid;
            float acc = 0.f;
#pragma unroll 8
            for (int c = 0; c < 64; c++) acc += sy[nn][c] * sWs[c * 64 + d];
            g_s1[n * 64 + d] = acc;
        } else {
            int idx = tid - 64;
            int d = idx & 63, xx = idx >> 6;
            float acc = 0.f;
#pragma unroll 8
            for (int c = 0; c < 64; c++) acc += sy[nn][64 + c * 3 + xx] * sWv[c * 64 + d];
            g_v1[n * 192 + xx * 64 + d] = acc;
        }
    }
}

// -------- per-edge scalar math (W1 in regs); returns silu(h) for this lane --------
__device__ __forceinline__ float edge_scalar(float ev0, float ev1, float ev2, float l2,
                                             const float* w1r, float br,
                                             float& ea0, float& ea1, float& ea2) {
    const float PI = 3.14159265358979f;
    float elen = sqrtf(l2);
    float safe = fmaxf(elen, 1e-9f);
    float inv = 1.0f / safe;
    float u = fminf(2.f * (elen * (1.0f / MAXR) - 1.f), 0.f);  // clamp: cut=0 beyond MAXR
    float cut = 0.5f * (1.f - __cosf(PI * u));
    float ca = cut * 1.7320508075688772f * inv;
    ea0 = ca * ev0; ea1 = ca * ev1; ea2 = ca * ev2;
    float th = (PI / MAXR) * safe;
    float sk = __sinf(th), c2 = 2.f * __cosf(th), skm1 = 0.f;
    float fac = 2.5298221281347035f * inv;
    float hs = br;
#pragma unroll
    for (int k = 0; k < 8; k++) {
        hs += (fac * sk) * w1r[k];
        float t = c2 * sk - skm1; skm1 = sk; sk = t;
    }
    return hs / (1.f + __expf(-hs));  // silu
}

// W2 duplicated-bf16x2 layout: sW2d[k*32+lane] = {dup(w0),dup(w1),dup(w2),dup(w3)}
__device__ __forceinline__ void fill_w2d(uint4* sW2d, const float* rW2, int layer,
                                         int tid) {
    for (int t = tid; t < 1024; t += 256) {
        int k = t >> 5, ln = t & 31;
        const float* base = rW2 + layer * 4096 + k * 128;
        uint4 v;
        __nv_bfloat162 p0 = __float2bfloat162_rn(base[ln]);
        __nv_bfloat162 p1 = __float2bfloat162_rn(base[32 + ln]);
        __nv_bfloat162 p2 = __float2bfloat162_rn(base[64 + ln]);
        __nv_bfloat162 p3 = __float2bfloat162_rn(base[96 + ln]);
        v.x = *reinterpret_cast<unsigned*>(&p0);
        v.y = *reinterpret_cast<unsigned*>(&p1);
        v.z = *reinterpret_cast<unsigned*>(&p2);
        v.w = *reinterpret_cast<unsigned*>(&p3);
        sW2d[t] = v;
    }
}

// -------- edge: dst-sorted filtered list, 4-edge groups, 4 blocks/SM --------
__global__ void __launch_bounds__(256, 4) k_edge(const float* __restrict__ rW1,
                                                 const float* __restrict__ rb1,
                                                 const float* __restrict__ rW2,
                                                 int layer, int skip_s1) {
    __shared__ uint4 sW2d[1024];   // 16 KB
    int tid = threadIdx.x;
    int lane = tid & 31;
    fill_w2d(sW2d, rW2, layer, tid);
    float w1r[8];
#pragma unroll
    for (int k = 0; k < 8; k++) w1r[k] = rW1[layer * 256 + k * 32 + lane];
    float br = rb1[layer * 32 + lane];
    __syncthreads();
    int cnt = g_nesurv;
    int warp = (blockIdx.x * 256 + tid) >> 5;
    int nw = gridDim.x * 8;
    int K = (cnt + nw - 1) / nw;
    int e0 = warp * K;
    if (e0 >= cnt) return;
    int e1 = e0 + K; if (e1 > cnt) e1 = cnt;
    float4 acc0 = make_float4(0.f, 0.f, 0.f, 0.f);
    float4 acc1 = make_float4(0.f, 0.f, 0.f, 0.f);
    bool touched = false;
    int cur = -1;
    __nv_bfloat162 zz; zz.x = __float2bfloat16(0.f); zz.y = zz.x;
    for (int e = e0; e < e1; e += 4) {
        int cnt4 = e1 - e; if (cnt4 > 4) cnt4 = 4;
        int srcs[4], dsts[4];
        float hv4[4], eaX[4], eaY[4], eaZ[4];
#pragma unroll
        for (int i = 0; i < 4; i++) {
            int idx = (i < cnt4) ? (e + i) : (e + cnt4 - 1);
            int d = g_sdst[idx], s = g_ssrc[idx];
            srcs[i] = s; dsts[i] = d;
            float dp0 = g_pos[d * 3 + 0], dp1 = g_pos[d * 3 + 1], dp2 = g_pos[d * 3 + 2];
            float ev0 = g_pos[s * 3 + 0] - dp0;
            float ev1 = g_pos[s * 3 + 1] - dp1;
            float ev2 = g_pos[s * 3 + 2] - dp2;
            float l2 = ev0 * ev0 + ev1 * ev1 + ev2 * ev2;
            float h = edge_scalar(ev0, ev1, ev2, l2, w1r, br, eaX[i], eaY[i], eaZ[i]);
            hv4[i] = (i < cnt4) ? h : 0.f;   // padded edges contribute zero
        }
        // ---- grouped W2 matvec: 2 SHFL + 1 LDS.128 + 8 HFMA2 per k for 4 edges ----
        __nv_bfloat162 h01 = __floats2bfloat162_rn(hv4[0], hv4[1]);
        __nv_bfloat162 h23 = __floats2bfloat162_rn(hv4[2], hv4[3]);
        unsigned u01 = *reinterpret_cast<unsigned*>(&h01);
        unsigned u23 = *reinterpret_cast<unsigned*>(&h23);
        __nv_bfloat162 p0 = zz, p1 = zz, p2 = zz, p3 = zz;
        __nv_bfloat162 q0 = zz, q1 = zz, q2 = zz, q3 = zz;
#pragma unroll
        for (int k = 0; k < 32; k++) {
            unsigned s01 = __shfl_sync(0xffffffffu, u01, k);
            unsigned s23 = __shfl_sync(0xffffffffu, u23, k);
            uint4 wv = sW2d[k * 32 + lane];
            __nv_bfloat162 b01 = *reinterpret_cast<__nv_bfloat162*>(&s01);
            __nv_bfloat162 b23 = *reinterpret_cast<__nv_bfloat162*>(&s23);
            p0 = __hfma2(b01, *reinterpret_cast<__nv_bfloat162*>(&wv.x), p0);
            p1 = __hfma2(b01, *reinterpret_cast<__nv_bfloat162*>(&wv.y), p1);
            p2 = __hfma2(b01, *reinterpret_cast<__nv_bfloat162*>(&wv.z), p2);
            p3 = __hfma2(b01, *reinterpret_cast<__nv_bfloat162*>(&wv.w), p3);
            q0 = __hfma2(b23, *reinterpret_cast<__nv_bfloat162*>(&wv.x), q0);
            q1 = __hfma2(b23, *reinterpret_cast<__nv_bfloat162*>(&wv.y), q1);
            q2 = __hfma2(b23, *reinterpret_cast<__nv_bfloat162*>(&wv.z), q2);
            q3 = __hfma2(b23, *reinterpret_cast<__nv_bfloat162*>(&wv.w), q3);
        }
        float2 f0p = __bfloat1622float2(p0), f1p = __bfloat1622float2(p1);
        float2 f2p = __bfloat1622float2(p2), f3p = __bfloat1622float2(p3);
        float2 f0q = __bfloat1622float2(q0), f1q = __bfloat1622float2(q1);
        float2 f2q = __bfloat1622float2(q2), f3q = __bfloat1622float2(q3);
        float w0v[4] = {f0p.x, f0p.y, f0q.x, f0q.y};
        float w1v[4] = {f1p.x, f1p.y, f1q.x, f1q.y};
        float w2v[4] = {f2p.x, f2p.y, f2q.x, f2q.y};
        float w3v[4] = {f3p.x, f3p.y, f3q.x, f3q.y};
        // ---- accumulate each edge in order ----
#pragma unroll
        for (int i = 0; i < 4; i++) {
            int dst = dsts[i];
            if (dst != cur) {
                if (touched) {
                    float4* ap = reinterpret_cast<float4*>(g_agg + (size_t)cur * 256);
                    atomicAdd(ap + lane, acc0);
                    atomicAdd(ap + lane + 32, acc1);
                    acc0 = make_float4(0.f, 0.f, 0.f, 0.f);
                    acc1 = make_float4(0.f, 0.f, 0.f, 0.f);
                    touched = false;
                }
                cur = dst;
            }
            int src = srcs[i];
            float sa = 0.f, sb = 0.f;
            if (!skip_s1) {
                const float* s1p = g_s1 + (size_t)src * 64;
                sa = s1p[lane] * w0v[i];
                sb = s1p[lane + 32] * w1v[i];
            }
            const float* v1p = g_v1 + (size_t)src * 192;
            float ex = eaX[i], ey = eaY[i], ez = eaZ[i];
            float da = w2v[i] * (v1p[lane] * ex + v1p[64 + lane] * ey + v1p[128 + lane] * ez);
            float db = w3v[i] * (v1p[lane + 32] * ex + v1p[96 + lane] * ey + v1p[160 + lane] * ez);
            acc0.x += sa * ex; acc0.y += sa * ey; acc0.z += sa * ez; acc0.w += da;
            acc1.x += sb * ex; acc1.y += sb * ey; acc1.z += sb * ez; acc1.w += db;
            touched = true;
        }
    }
    if (touched) {
        float4* ap = reinterpret_cast<float4*>(g_agg + (size_t)cur * 256);
        atomicAdd(ap + lane, acc0);
        atomicAdd(ap + lane + 32, acc1);
    }
}

// ------ post v8: float4 input LDS, float2 tasks, 4 blocks/SM ------
__global__ void __launch_bounds__(256, 4) k_post(const float* __restrict__ lin2s,
                                                 const float* __restrict__ lin2v,
                                                 const float* __restrict__ sis,
                                                 const float* __restrict__ siv,
                                                 const float* __restrict__ hv,
                                                 const float* __restrict__ mv,
                                                 int layer, int cur,
                                                 float* __restrict__ outp) {
    __shared__ float s_Q[128];
    __shared__ __align__(16) float s_ys[8][64], s_aggs[8][64];
    __shared__ __align__(16) float s_yv[8][192], s_aggv[8][192];   // [xx*64+c]
    __shared__ __align__(16) float s_outs[8][128];
    __shared__ __align__(16) float s_outv[8][192];
    __shared__ __align__(16) float s_y2s[8][64];
    __shared__ __align__(16) float s_y2v[8][192];
    __shared__ float s_newv[8][192];
    int tid = threadIdx.x;
    int wid = tid >> 5;
    if (tid < 128) s_Q[tid] = g_Q[tid];
    float hh = hv[layer] * hv[layer];
    float m = mv[layer];
    float* ys_new = g_ys[cur ^ 1];
    float* yv_new = g_yv[cur ^ 1];
    const float* ys_cur = g_ys[cur];
    const float* yv_cur = g_yv[cur];
    for (int it = 0; it < 2; it++) {
        int pbase = blockIdx.x * 16 + it * 8;
        for (int t = tid; t < 512; t += 256) {
            int node = t >> 6, j = t & 63;
            int n = g_nidx[pbase + node];
            if (n >= 0) {
                s_ys[node][j] = ys_cur[n * 64 + j];
                float4 a4 = ((const float4*)g_agg)[n * 64 + j];
                if (layer == 0)
                    ((float4*)g_agg)[n * 64 + j] = make_float4(0.f, 0.f, 0.f, 0.f);
                s_aggs[node][j] = a4.w * INV_NN;
                s_aggv[node][j] = a4.x * INV_NN;
                s_aggv[node][64 + j] = a4.y * INV_NN;
                s_aggv[node][128 + j] = a4.z * INV_NN;
                const float* yvp = yv_cur + n * 192 + j * 3;
                s_yv[node][j] = yvp[0];
                s_yv[node][64 + j] = yvp[1];
                s_yv[node][128 + j] = yvp[2];
            }
        }
        __syncthreads();
        int a = g_nattr[pbase];   // chunk is attr-uniform
        if (wid < 5) {
            const float2 *wp, *bp;
            int wstr;
            const float *in1, *in2;
            int istr;
            float2* o2;
            int ostr;
            if (tid < 64) {
                int j = tid;
                wp = (const float2*)(lin2s + layer * 8192) + j;
                bp = (const float2*)(g_Bs + (size_t)(layer * 100 + a) * 8192) + j;
                wstr = 64;
                in1 = &s_aggs[0][0]; in2 = &s_ys[0][0]; istr = 64;
                o2 = (float2*)&s_outs[0][0] + j; ostr = 64;
            } else {
                int id = tid - 64, xx = id >> 5, j = id & 31;
                wp = (const float2*)(lin2v + layer * 4096) + j;
                bp = (const float2*)(g_Bv + (size_t)(layer * 100 + a) * 4096) + j;
                wstr = 32;
                in1 = &s_aggv[0][xx * 64]; in2 = &s_yv[0][xx * 64]; istr = 192;
                o2 = (float2*)&s_outv[0][0] + xx * 32 + j; ostr = 96;
            }
            float2 acc[8];
#pragma unroll
            for (int nn = 0; nn < 8; nn++) acc[nn] = make_float2(0.f, 0.f);
            for (int c = 0; c < 64; c += 4) {
                float2 w0 = __ldg(wp + (c + 0) * wstr);
                float2 w1 = __ldg(wp + (c + 1) * wstr);
                float2 w2 = __ldg(wp + (c + 2) * wstr);
                float2 w3 = __ldg(wp + (c + 3) * wstr);
                float2 b0 = __ldg(bp + (c + 0) * wstr);
                float2 b1 = __ldg(bp + (c + 1) * wstr);
                float2 b2 = __ldg(bp + (c + 2) * wstr);
                float2 b3 = __ldg(bp + (c + 3) * wstr);
#pragma unroll
                for (int nn = 0; nn < 8; nn++) {
                    float4 u1 = *(const float4*)(in1 + nn * istr + c);
                    float4 u2 = *(const float4*)(in2 + nn * istr + c);
                    acc[nn].x += u1.x * w0.x + u2.x * b0.x;
                    acc[nn].y += u1.x * w0.y + u2.x * b0.y;
                    acc[nn].x += u1.y * w1.x + u2.y * b1.x;
                    acc[nn].y += u1.y * w1.y + u2.y * b1.y;
                    acc[nn].x += u1.z * w2.x + u2.z * b2.x;
                    acc[nn].y += u1.z * w2.y + u2.z * b2.y;
                    acc[nn].x += u1.w * w3.x + u2.w * b3.x;
                    acc[nn].y += u1.w * w3.y + u2.w * b3.y;
                }
            }
#pragma unroll
            for (int nn = 0; nn < 8; nn++) o2[nn * ostr] = acc[nn];
        } else if (wid == 5) {
            int j = tid - 160;
            const float2* wp = (const float2*)(sis + layer * 4096) + j;
            float2 acc[8];
#pragma unroll
            for (int nn = 0; nn < 8; nn++) acc[nn] = make_float2(0.f, 0.f);
            for (int c = 0; c < 64; c += 4) {
                float2 w0 = __ldg(wp + (c + 0) * 32);
                float2 w1 = __ldg(wp + (c + 1) * 32);
                float2 w2 = __ldg(wp + (c + 2) * 32);
                float2 w3 = __ldg(wp + (c + 3) * 32);
#pragma unroll
                for (int nn = 0; nn < 8; nn++) {
                    float4 u = *(const float4*)(&s_ys[nn][c]);
                    acc[nn].x += u.x * w0.x + u.y * w1.x + u.z * w2.x + u.w * w3.x;
                    acc[nn].y += u.x * w0.y + u.y * w1.y + u.z * w2.y + u.w * w3.y;
                }
            }
#pragma unroll
            for (int nn = 0; nn < 8; nn++)
                ((float2*)&s_y2s[0][0])[nn * 32 + j] = acc[nn];
        } else if (tid < 240) {
            int id = tid - 192, xx = id >> 4, j = id & 15;
            const float4* wp = (const float4*)(siv + layer * 4096) + j;
            const float* in = &s_yv[0][xx * 64];
            float4 acc[8];
#pragma unroll
            for (int nn = 0; nn < 8; nn++) acc[nn] = make_float4(0.f, 0.f, 0.f, 0.f);
            for (int c = 0; c < 64; c += 4) {
                float4 w0 = __ldg(wp + (c + 0) * 16);
                float4 w1 = __ldg(wp + (c + 1) * 16);
                float4 w2 = __ldg(wp + (c + 2) * 16);
                float4 w3 = __ldg(wp + (c + 3) * 16);
#pragma unroll
                for (int nn = 0; nn < 8; nn++) {
                    float4 u = *(const float4*)(in + nn * 192 + c);
                    acc[nn].x += u.x * w0.x + u.y * w1.x + u.z * w2.x + u.w * w3.x;
                    acc[nn].y += u.x * w0.y + u.y * w1.y + u.z * w2.y + u.w * w3.y;
                    acc[nn].z += u.x * w0.z + u.y * w1.z + u.z * w2.z + u.w * w3.z;
                    acc[nn].w += u.x * w0.w + u.y * w1.w + u.z * w2.w + u.w * w3.w;
                }
            }
#pragma unroll
            for (int nn = 0; nn < 8; nn++)
                ((float4*)&s_y2v[0][0])[nn * 48 + xx * 16 + j] = acc[nn];
        }
        __syncthreads();
        for (int t = tid; t < 512; t += 256) {
            int node = t >> 6, c = t & 63;
            int n = g_nidx[pbase + node];
            if (n >= 0) {
                float os = s_outs[node][c];
                float gs = os / (1.f + __expf(-os));
                float gate = 1.f / (1.f + __expf(-s_outs[node][64 + c]));
                float yo = ys_new[n * 64 + c];
                float ns = 2.f * s_ys[node][c] - yo + hh * (m * gs + (m - 1.f) * s_y2s[node][c]);
                ys_new[n * 64 + c] = ns;
#pragma unroll
                for (int xx = 0; xx < 3; xx++) {
                    float yov = yv_new[n * 192 + c * 3 + xx];
                    float nv = 2.f * s_yv[node][xx * 64 + c] - yov +
                               hh * (m * gate * s_outv[node][xx * 64 + c] +
                                     (m - 1.f) * s_y2v[node][xx * 64 + c]);
                    yv_new[n * 192 + c * 3 + xx] = nv;
                    s_newv[node][xx * 64 + c] = nv;
                }
            }
        }
        __syncthreads();
        if (tid < 48) {
            int node = tid / 6, r = tid % 6, k = r / 3, xx = r % 3;
            int n = g_nidx[pbase + node];
            if (n >= 0) {
                float acc = 0.f;
#pragma unroll 8
                for (int c = 0; c < 64; c++) acc += s_newv[node][xx * 64 + c] * s_Q[c * 2 + k];
                if (layer == 0) {
                    if (k == 0) g_pos[n * 3 + xx] = acc;
                } else {
                    outp[n * 6 + k * 3 + xx] = acc;
                }
            }
        }
        __syncthreads();
    }
}

// ---------------- launch ----------------
extern "C" void kernel_launch(void* const* d_in, const int* in_sizes, int n_in,
                              void* d_out, int out_size) {
    const float* x        = (const float*)d_in[0];
    const int*   attr     = (const int*)d_in[2];
    const int*   esrc     = (const int*)d_in[3];
    const int*   edst     = (const int*)d_in[4];
    const float* emb      = (const float*)d_in[5];
    const float* uplift   = (const float*)d_in[6];
    const float* h        = (const float*)d_in[7];
    const float* mix      = (const float*)d_in[8];
    const float* rW1      = (const float*)d_in[9];
    const float* rb1      = (const float*)d_in[10];
    const float* rW2      = (const float*)d_in[11];
    const float* lin1s    = (const float*)d_in[12];
    const float* lin1v    = (const float*)d_in[13];
    const float* lin2s    = (const float*)d_in[14];
    const float* lin2v    = (const float*)d_in[15];
    const float* scs      = (const float*)d_in[16];
    const float* scv      = (const float*)d_in[17];
    const float* sis      = (const float*)d_in[18];
    const float* siv      = (const float*)d_in[19];
    float* out = (float*)d_out;

    const int PB = NPAD / 16;  // 1300

    k_init<<<6537, 256>>>(x, uplift, emb, scs, scv, lin1v, attr, esrc, edst); // 0
    k_scan_e<<<1, 512>>>();                                                   // 1
    k_scat_e<<<1280, 256>>>(esrc, edst, x);                                   // 2
    k_edge<<<2000, 256>>>(rW1, rb1, rW2, 0, 1);                               // 3 <- profiled
    k_post<<<PB, 256>>>(lin2s, lin2v, sis, siv, h, mix, 0, 0, out);           // 4
    k_pre<<<NN / 8, 256>>>(lin1s, lin1v, 1, 1);                               // 5 (+cnt cleanup)
    k_edge<<<2000, 256>>>(rW1, rb1, rW2, 1, 0);                               // 6
    k_post<<<PB, 256>>>(lin2s, lin2v, sis, siv, h, mix, 1, 1, out);           // 7
}

// round 15
// speedup vs baseline: 1.0445x; 1.0445x over previous
#include <cuda_runtime.h>
#include <cuda_bf16.h>
#include <math.h>

#define NN 20000
#define NE 640000
#define NL 2
#define MAXR 2.5f
#define INV_NN 0.17677669529663687f   // 1/sqrt(32)
#define NPAD 20800                    // attr-sorted node list padded to 8-aligned segments

// ---------------- scratch (device globals; no allocs) ----------------
static __device__ float g_Q[64 * 2];
static __device__ float g_ys[2][NN * 64];
static __device__ float g_yv[2][NN * 192];
static __device__ float g_s1[NN * 64];
static __device__ float g_v1[NN * 192];          // [n][3][64] x-major
static __device__ float g_agg[NN * 256];         // (n, c, 4): vx,vy,vz,s
static __device__ float g_pos[NN * 3];
static __device__ float g_Bs[NL * 100 * 64 * 128];
static __device__ float g_Bv[NL * 100 * 64 * 64];
// edge sort (by dst, filtered); counters zeroed by k_pre of the PREVIOUS call (.bss first)
static __device__ int g_ecnt[NN];
static __device__ int g_eoff[NN];
static __device__ int g_eppos[NN];
static __device__ int g_nesurv;
static __device__ int g_ssrc[NE];
static __device__ int g_sdst[NE];
// node sort (by attr), 8-aligned segments, -1 = sentinel
static __device__ int g_nidx[NPAD];
static __device__ int g_nattr[NPAD];

// ---- fused init: Q + y init + layer0 v1 + B precompute (tiled) + node sort + hist ----
__global__ void __launch_bounds__(256) k_init(const float* __restrict__ x,
                                              const float* __restrict__ M,
                                              const float* __restrict__ emb,
                                              const float* __restrict__ scs,
                                              const float* __restrict__ scv,
                                              const float* __restrict__ lin1v,
                                              const int* __restrict__ attr,
                                              const int* __restrict__ esrc,
                                              const int* __restrict__ edst) {
    int tid = threadIdx.x;
    if (blockIdx.x < 5000) {
        __shared__ double dI[3];
        __shared__ float sQ[128];
        __shared__ float sR[128];
        if (tid < 32) {
            double m0a = M[2 * tid], m1a = M[2 * tid + 1];
            double m0b = M[2 * (tid + 32)], m1b = M[2 * (tid + 32) + 1];
            double pa = m0a * m0a + m0b * m0b;
            double pb = m0a * m1a + m0b * m1b;
            double pc = m1a * m1a + m1b * m1b;
#pragma unroll
            for (int off = 16; off > 0; off >>= 1) {
                pa += __shfl_down_sync(0xffffffffu, pa, off);
                pb += __shfl_down_sync(0xffffffffu, pb, off);
                pc += __shfl_down_sync(0xffffffffu, pc, off);
            }
            if (tid == 0) {
                double det = pa * pc - pb * pb;
                double s = sqrt(det);
                double t = pa + pc;
                double denom = sqrt(t + 2.0 * s);
                double p00 = (pa + s) / denom, p01 = pb / denom, p11 = (pc + s) / denom;
                double pdet = p00 * p11 - p01 * p01;
                dI[0] = p11 / pdet; dI[1] = -p01 / pdet; dI[2] = p00 / pdet;
            }
        }
        __syncthreads();
        if (tid < 64) {
            double m0 = M[2 * tid], m1 = M[2 * tid + 1];
            sQ[2 * tid]     = (float)(m0 * dI[0] + m1 * dI[1]);
            sQ[2 * tid + 1] = (float)(m0 * dI[1] + m1 * dI[2]);
        }
        __syncthreads();
        if (blockIdx.x == 0 && tid < 128) g_Q[tid] = sQ[tid];
        if (tid < 128) {
            int k = tid >> 6, d = tid & 63;
            float acc = 0.f;
#pragma unroll 8
            for (int c = 0; c < 64; c++) acc += sQ[c * 2 + k] * lin1v[c * 64 + d];
            sR[k * 64 + d] = acc;
        }
        __syncthreads();
        int i = blockIdx.x * 256 + tid;
        if (i >= NN * 64) return;
        int n = i >> 6, c = i & 63;
        float q0 = sQ[c * 2], q1 = sQ[c * 2 + 1];
        const float* xp = x + n * 6;
        float v0 = xp[0] * q0 + xp[3] * q1;
        float v1 = xp[1] * q0 + xp[4] * q1;
        float v2 = xp[2] * q0 + xp[5] * q1;
        int base = n * 192 + c * 3;
        g_yv[0][base + 0] = v0; g_yv[0][base + 1] = v1; g_yv[0][base + 2] = v2;
        g_yv[1][base + 0] = v0; g_yv[1][base + 1] = v1; g_yv[1][base + 2] = v2;
        g_ys[0][i] = 0.f; g_ys[1][i] = 0.f;
        if (c < 3) g_pos[n * 3 + c] = xp[c];
        reinterpret_cast<float4*>(g_agg)[i] = make_float4(0.f, 0.f, 0.f, 0.f);
        int d = c;
        float r0 = sR[d], r1 = sR[64 + d];
#pragma unroll
        for (int xx = 0; xx < 3; xx++)
            g_v1[n * 192 + xx * 64 + d] = xp[xx] * r0 + xp[3 + xx] * r1;
    } else if (blockIdx.x < 5256) {
        // ---- B precompute, tiled: one block per (l,c); W column in regs ----
        int b = blockIdx.x - 5000;
        __shared__ __align__(16) float semb[3200];   // 100 x 32 (16B-aligned for LDS.128)
        for (int i = tid; i < 3200; i += 256) semb[i] = emb[i];
        __syncthreads();
        if (b < 128) {
            int l = b >> 6, c = b & 63;
            int o = tid & 127, ah = tid >> 7;       // a-half: 0 -> [0,50), 1 -> [50,100)
            float wcol[32];
            const float* w = scs + ((size_t)(l * 64 + c) * 32) * 128 + o;
#pragma unroll
            for (int e2 = 0; e2 < 32; e2++) wcol[e2] = w[e2 * 128];
            int a0 = ah * 50, a1 = a0 + 50;
            for (int a = a0; a < a1; a++) {
                const float4* em = (const float4*)(semb + a * 32);
                float acc = 0.f;
#pragma unroll
                for (int e4 = 0; e4 < 8; e4++) {
                    float4 u = em[e4];
                    acc += u.x * wcol[e4 * 4] + u.y * wcol[e4 * 4 + 1] +
                           u.z * wcol[e4 * 4 + 2] + u.w * wcol[e4 * 4 + 3];
                }
                g_Bs[((size_t)(l * 100 + a) * 64 + c) * 128 + o] = acc;
            }
        } else {
            int b2 = b - 128;
            int l = b2 >> 6, c = b2 & 63;
            int o = tid & 63, ah = tid >> 6;        // a-quarter: 25 each
            float wcol[32];
            const float* w = scv + ((size_t)(l * 64 + c) * 32) * 64 + o;
#pragma unroll
            for (int e2 = 0; e2 < 32; e2++) wcol[e2] = w[e2 * 64];
            int a0 = ah * 25, a1 = a0 + 25;
            for (int a = a0; a < a1; a++) {
                const float4* em = (const float4*)(semb + a * 32);
                float acc = 0.f;
#pragma unroll
                for (int e4 = 0; e4 < 8; e4++) {
                    float4 u = em[e4];
                    acc += u.x * wcol[e4 * 4] + u.y * wcol[e4 * 4 + 1] +
                           u.z * wcol[e4 * 4 + 2] + u.w * wcol[e4 * 4 + 3];
                }
                g_Bv[((size_t)(l * 100 + a) * 64 + c) * 64 + o] = acc;
            }
        }
    } else if (blockIdx.x == 5256) {
        // single-block node counting sort by attr, segments padded to 8
        __shared__ int scnt[128], soff[128], spos[128];
        if (tid < 128) { scnt[tid] = 0; spos[tid] = 0; }
        __syncthreads();
        for (int n = tid; n < NN; n += 256) atomicAdd(&scnt[attr[n]], 1);
        __syncthreads();
        int pc = 0;
        if (tid < 128) { pc = (scnt[tid] + 7) & ~7; soff[tid] = pc; }
        __syncthreads();
        for (int off = 1; off < 128; off <<= 1) {
            int v = 0;
            if (tid < 128 && tid >= off) v = soff[tid - off];
            __syncthreads();
            if (tid < 128) soff[tid] += v;
            __syncthreads();
        }
        if (tid < 128) soff[tid] -= pc;  // exclusive, 8-aligned
        __syncthreads();
        for (int i = tid; i < NPAD; i += 256) g_nidx[i] = -1;
        __syncthreads();
        for (int n = tid; n < NN; n += 256) {
            int a = attr[n];
            int p = soff[a] + atomicAdd(&spos[a], 1);
            g_nidx[p] = n;
            g_nattr[p] = a;
        }
    } else {
        // FILTERED edge histogram (layer-0 positions = x)
        for (int e = (blockIdx.x - 5257) * 256 + tid; e < NE; e += 1280 * 256) {
            int s = esrc[e], d = edst[e];
            float dx = x[s * 6 + 0] - x[d * 6 + 0];
            float dy = x[s * 6 + 1] - x[d * 6 + 1];
            float dz = x[s * 6 + 2] - x[d * 6 + 2];
            if (dx * dx + dy * dy + dz * dz < MAXR * MAXR)
                atomicAdd(&g_ecnt[d], 1);
        }
    }
}

// ---------------- edge offset scan (writes surviving count) ----------------
__global__ void __launch_bounds__(512) k_scan_e() {
    __shared__ int sp[512];
    int t = threadIdx.x;
    const int CH = 40;
    int base = t * CH;
    int part = 0;
    for (int i = 0; i < CH; i++) {
        int idx = base + i;
        if (idx < NN) part += g_ecnt[idx];
    }
    sp[t] = part;
    __syncthreads();
    for (int off = 1; off < 512; off <<= 1) {
        int v = (t >= off) ? sp[t - off] : 0;
        __syncthreads();
        sp[t] += v;
        __syncthreads();
    }
    if (t == 511) g_nesurv = sp[511];
    int run = sp[t] - part;
    for (int i = 0; i < CH; i++) {
        int idx = base + i;
        if (idx < NN) { g_eoff[idx] = run; run += g_ecnt[idx]; }
    }
}

// ---------------- filtered edge scatter ----------------
__global__ void k_scat_e(const int* __restrict__ esrc, const int* __restrict__ edst,
                         const float* __restrict__ x) {
    for (int e = blockIdx.x * 256 + threadIdx.x; e < NE; e += 1280 * 256) {
        int s = esrc[e], d = edst[e];
        float dx = x[s * 6 + 0] - x[d * 6 + 0];
        float dy = x[s * 6 + 1] - x[d * 6 + 1];
        float dz = x[s * 6 + 2] - x[d * 6 + 2];
        if (dx * dx + dy * dy + dz * dz < MAXR * MAXR) {
            int p = g_eoff[d] + atomicAdd(&g_eppos[d], 1);
            g_ssrc[p] = s;
            g_sdst[p] = d;
        }
    }
}

// ------- pre (layer 1) + sort-counter cleanup for next call's hist -------
__global__ void __launch_bounds__(256) k_pre(const float* __restrict__ lin1s,
                                             const float* __restrict__ lin1v,
                                             int layer, int cur) {
    __shared__ float sWs[4096], sWv[4096];
    __shared__ float sy[8][256];
    int tid = threadIdx.x;
    {
        int i = blockIdx.x * 256 + tid;
        if (i < NN) { g_ecnt[i] = 0; g_eppos[i] = 0; }
    }
    const float* Ws = lin1s + layer * 4096;
    const float* Wv = lin1v + layer * 4096;
    for (int k = tid; k < 4096; k += 256) { sWs[k] = Ws[k]; sWv[k] = Wv[k]; }
    const float* ys = g_ys[cur];
    const float* yv = g_yv[cur];
    int n0 = blockIdx.x * 8;
    for (int k = tid; k < 2048; k += 256) {
        int nn = k >> 8, j = k & 255;
        int n = n0 + nn;
        sy[nn][j] = (j < 64) ? ys[n * 64 + j] : yv[n * 192 + j - 64];
    }
    __syncthreads();
    for (int nn = 0; nn < 8; nn++) {
        int n = n0 + nn;
        if (tid < 64) {
            int d = tid;
            float acc = 0.f;
#pragma unroll 8
            for (int c = 0; c < 64; c++) acc += sy[nn][c] * sWs[c * 64 + d];
            g_s1[n * 64 + d] = acc;
        } else {
            int idx = tid - 64;
            int d = idx & 63, xx = idx >> 6;
            float acc = 0.f;
#pragma unroll 8
            for (int c = 0; c < 64; c++) acc += sy[nn][64 + c * 3 + xx] * sWv[c * 64 + d];
            g_v1[n * 192 + xx * 64 + d] = acc;
        }
    }
}

// -------- per-edge scalar math (W1 in regs); cut = sin^2(th) identity --------
__device__ __forceinline__ float edge_scalar(float ev0, float ev1, float ev2, float l2,
                                             const float* w1r, float br,
                                             float& ea0, float& ea1, float& ea2) {
    const float PI = 3.14159265358979f;
    float elen = sqrtf(l2);
    float safe = fmaxf(elen, 1e-9f);
    float inv = 1.0f / safe;
    float th = (PI / MAXR) * safe;
    float sk = __sinf(th), c2 = 2.f * __cosf(th);
    // cut = 0.5*(1-cos(pi*u)) with u=2*(elen/R-1)  ==  sin^2(pi*elen/R) = sk*sk
    float ca = sk * sk * 1.7320508075688772f * inv;
    ea0 = ca * ev0; ea1 = ca * ev1; ea2 = ca * ev2;
    float skm1 = 0.f, skk = sk;
    float fac = 2.5298221281347035f * inv;
    float hs = br;
#pragma unroll
    for (int k = 0; k < 8; k++) {
        hs += (fac * skk) * w1r[k];
        float t = c2 * skk - skm1; skm1 = skk; skk = t;
    }
    return hs / (1.f + __expf(-hs));  // silu
}

// W2 duplicated-bf16x2 layout: sW2d[k*32+lane] = {dup(w0),dup(w1),dup(w2),dup(w3)}
__device__ __forceinline__ void fill_w2d(uint4* sW2d, const float* rW2, int layer,
                                         int tid) {
    for (int t = tid; t < 1024; t += 256) {
        int k = t >> 5, ln = t & 31;
        const float* base = rW2 + layer * 4096 + k * 128;
        uint4 v;
        __nv_bfloat162 p0 = __float2bfloat162_rn(base[ln]);
        __nv_bfloat162 p1 = __float2bfloat162_rn(base[32 + ln]);
        __nv_bfloat162 p2 = __float2bfloat162_rn(base[64 + ln]);
        __nv_bfloat162 p3 = __float2bfloat162_rn(base[96 + ln]);
        v.x = *reinterpret_cast<unsigned*>(&p0);
        v.y = *reinterpret_cast<unsigned*>(&p1);
        v.z = *reinterpret_cast<unsigned*>(&p2);
        v.w = *reinterpret_cast<unsigned*>(&p3);
        sW2d[t] = v;
    }
}

// -------- edge: dst-sorted filtered list, 4-edge groups (natural regs) --------
__global__ void __launch_bounds__(256) k_edge(const float* __restrict__ rW1,
                                              const float* __restrict__ rb1,
                                              const float* __restrict__ rW2,
                                              int layer, int skip_s1) {
    __shared__ uint4 sW2d[1024];   // 16 KB
    int tid = threadIdx.x;
    int lane = tid & 31;
    fill_w2d(sW2d, rW2, layer, tid);
    float w1r[8];
#pragma unroll
    for (int k = 0; k < 8; k++) w1r[k] = rW1[layer * 256 + k * 32 + lane];
    float br = rb1[layer * 32 + lane];
    __syncthreads();
    int cnt = g_nesurv;
    int warp = (blockIdx.x * 256 + tid) >> 5;
    int nw = gridDim.x * 8;
    int K = (cnt + nw - 1) / nw;
    int e0 = warp * K;
    if (e0 >= cnt) return;
    int e1 = e0 + K; if (e1 > cnt) e1 = cnt;
    float4 acc0 = make_float4(0.f, 0.f, 0.f, 0.f);
    float4 acc1 = make_float4(0.f, 0.f, 0.f, 0.f);
    bool touched = false;
    int cur = -1;
    __nv_bfloat162 zz; zz.x = __float2bfloat16(0.f); zz.y = zz.x;
    for (int e = e0; e < e1; e += 4) {
        int cnt4 = e1 - e; if (cnt4 > 4) cnt4 = 4;
        int srcs[4], dsts[4];
        float hv4[4], eaX[4], eaY[4], eaZ[4];
#pragma unroll
        for (int i = 0; i < 4; i++) {
            int idx = (i < cnt4) ? (e + i) : (e + cnt4 - 1);
            int d = g_sdst[idx], s = g_ssrc[idx];
            srcs[i] = s; dsts[i] = d;
            float dp0 = g_pos[d * 3 + 0], dp1 = g_pos[d * 3 + 1], dp2 = g_pos[d * 3 + 2];
            float ev0 = g_pos[s * 3 + 0] - dp0;
            float ev1 = g_pos[s * 3 + 1] - dp1;
            float ev2 = g_pos[s * 3 + 2] - dp2;
            float l2 = ev0 * ev0 + ev1 * ev1 + ev2 * ev2;
            float h = edge_scalar(ev0, ev1, ev2, l2, w1r, br, eaX[i], eaY[i], eaZ[i]);
            hv4[i] = (i < cnt4) ? h : 0.f;   // padded edges contribute zero
        }
        // ---- grouped W2 matvec: 2 SHFL + 1 LDS.128 + 8 HFMA2 per k for 4 edges ----
        __nv_bfloat162 h01 = __floats2bfloat162_rn(hv4[0], hv4[1]);
        __nv_bfloat162 h23 = __floats2bfloat162_rn(hv4[2], hv4[3]);
        unsigned u01 = *reinterpret_cast<unsigned*>(&h01);
        unsigned u23 = *reinterpret_cast<unsigned*>(&h23);
        __nv_bfloat162 p0 = zz, p1 = zz, p2 = zz, p3 = zz;
        __nv_bfloat162 q0 = zz, q1 = zz, q2 = zz, q3 = zz;
#pragma unroll
        for (int k = 0; k < 32; k++) {
            unsigned s01 = __shfl_sync(0xffffffffu, u01, k);
            unsigned s23 = __shfl_sync(0xffffffffu, u23, k);
            uint4 wv = sW2d[k * 32 + lane];
            __nv_bfloat162 b01 = *reinterpret_cast<__nv_bfloat162*>(&s01);
            __nv_bfloat162 b23 = *reinterpret_cast<__nv_bfloat162*>(&s23);
            p0 = __hfma2(b01, *reinterpret_cast<__nv_bfloat162*>(&wv.x), p0);
            p1 = __hfma2(b01, *reinterpret_cast<__nv_bfloat162*>(&wv.y), p1);
            p2 = __hfma2(b01, *reinterpret_cast<__nv_bfloat162*>(&wv.z), p2);
            p3 = __hfma2(b01, *reinterpret_cast<__nv_bfloat162*>(&wv.w), p3);
            q0 = __hfma2(b23, *reinterpret_cast<__nv_bfloat162*>(&wv.x), q0);
            q1 = __hfma2(b23, *reinterpret_cast<__nv_bfloat162*>(&wv.y), q1);
            q2 = __hfma2(b23, *reinterpret_cast<__nv_bfloat162*>(&wv.z), q2);
            q3 = __hfma2(b23, *reinterpret_cast<__nv_bfloat162*>(&wv.w), q3);
        }
        float2 f0p = __bfloat1622float2(p0), f1p = __bfloat1622float2(p1);
        float2 f2p = __bfloat1622float2(p2), f3p = __bfloat1622float2(p3);
        float2 f0q = __bfloat1622float2(q0), f1q = __bfloat1622float2(q1);
        float2 f2q = __bfloat1622float2(q2), f3q = __bfloat1622float2(q3);
        float w0v[4] = {f0p.x, f0p.y, f0q.x, f0q.y};
        float w1v[4] = {f1p.x, f1p.y, f1q.x, f1q.y};
        float w2v[4] = {f2p.x, f2p.y, f2q.x, f2q.y};
        float w3v[4] = {f3p.x, f3p.y, f3q.x, f3q.y};
        // ---- accumulate each edge in order ----
#pragma unroll
        for (int i = 0; i < 4; i++) {
            int dst = dsts[i];
            if (dst != cur) {
                if (touched) {
                    float4* ap = reinterpret_cast<float4*>(g_agg + (size_t)cur * 256);
                    atomicAdd(ap + lane, acc0);
                    atomicAdd(ap + lane + 32, acc1);
                    acc0 = make_float4(0.f, 0.f, 0.f, 0.f);
                    acc1 = make_float4(0.f, 0.f, 0.f, 0.f);
                    touched = false;
                }
                cur = dst;
            }
            int src = srcs[i];
            float sa = 0.f, sb = 0.f;
            if (!skip_s1) {
                const float* s1p = g_s1 + (size_t)src * 64;
                sa = s1p[lane] * w0v[i];
                sb = s1p[lane + 32] * w1v[i];
            }
            const float* v1p = g_v1 + (size_t)src * 192;
            float ex = eaX[i], ey = eaY[i], ez = eaZ[i];
            float da = w2v[i] * (v1p[lane] * ex + v1p[64 + lane] * ey + v1p[128 + lane] * ez);
            float db = w3v[i] * (v1p[lane + 32] * ex + v1p[96 + lane] * ey + v1p[160 + lane] * ez);
            acc0.x += sa * ex; acc0.y += sa * ey; acc0.z += sa * ez; acc0.w += da;
            acc1.x += sb * ex; acc1.y += sb * ey; acc1.z += sb * ez; acc1.w += db;
            touched = true;
        }
    }
    if (touched) {
        float4* ap = reinterpret_cast<float4*>(g_agg + (size_t)cur * 256);
        atomicAdd(ap + lane, acc0);
        atomicAdd(ap + lane + 32, acc1);
    }
}

// ------ post v7: float4 input LDS, float2 tasks, zeroes agg (layer 0) ------
__global__ void __launch_bounds__(256, 3) k_post(const float* __restrict__ lin2s,
                                                 const float* __restrict__ lin2v,
                                                 const float* __restrict__ sis,
                                                 const float* __restrict__ siv,
                                                 const float* __restrict__ hv,
                                                 const float* __restrict__ mv,
                                                 int layer, int cur,
                                                 float* __restrict__ outp) {
    __shared__ float s_Q[128];
    __shared__ __align__(16) float s_ys[8][64], s_aggs[8][64];
    __shared__ __align__(16) float s_yv[8][192], s_aggv[8][192];   // [xx*64+c]
    __shared__ __align__(16) float s_outs[8][128];
    __shared__ __align__(16) float s_outv[8][192];
    __shared__ __align__(16) float s_y2s[8][64];
    __shared__ __align__(16) float s_y2v[8][192];
    __shared__ float s_newv[8][192];
    int tid = threadIdx.x;
    int wid = tid >> 5;
    if (tid < 128) s_Q[tid] = g_Q[tid];
    float hh = hv[layer] * hv[layer];
    float m = mv[layer];
    float* ys_new = g_ys[cur ^ 1];
    float* yv_new = g_yv[cur ^ 1];
    const float* ys_cur = g_ys[cur];
    const float* yv_cur = g_yv[cur];
    for (int it = 0; it < 2; it++) {
        int pbase = blockIdx.x * 16 + it * 8;
        for (int t = tid; t < 512; t += 256) {
            int node = t >> 6, j = t & 63;
            int n = g_nidx[pbase + node];
            if (n >= 0) {
                s_ys[node][j] = ys_cur[n * 64 + j];
                float4 a4 = ((const float4*)g_agg)[n * 64 + j];
                if (layer == 0)
                    ((float4*)g_agg)[n * 64 + j] = make_float4(0.f, 0.f, 0.f, 0.f);
                s_aggs[node][j] = a4.w * INV_NN;
                s_aggv[node][j] = a4.x * INV_NN;
                s_aggv[node][64 + j] = a4.y * INV_NN;
                s_aggv[node][128 + j] = a4.z * INV_NN;
                const float* yvp = yv_cur + n * 192 + j * 3;
                s_yv[node][j] = yvp[0];
                s_yv[node][64 + j] = yvp[1];
                s_yv[node][128 + j] = yvp[2];
            }
        }
        __syncthreads();
        int a = g_nattr[pbase];   // chunk is attr-uniform
        if (wid < 5) {
            const float2 *wp, *bp;
            int wstr;
            const float *in1, *in2;
            int istr;
            float2* o2;
            int ostr;
            if (tid < 64) {
                int j = tid;
                wp = (const float2*)(lin2s + layer * 8192) + j;
                bp = (const float2*)(g_Bs + (size_t)(layer * 100 + a) * 8192) + j;
                wstr = 64;
                in1 = &s_aggs[0][0]; in2 = &s_ys[0][0]; istr = 64;
                o2 = (float2*)&s_outs[0][0] + j; ostr = 64;
            } else {
                int id = tid - 64, xx = id >> 5, j = id & 31;
                wp = (const float2*)(lin2v + layer * 4096) + j;
                bp = (const float2*)(g_Bv + (size_t)(layer * 100 + a) * 4096) + j;
                wstr = 32;
                in1 = &s_aggv[0][xx * 64]; in2 = &s_yv[0][xx * 64]; istr = 192;
                o2 = (float2*)&s_outv[0][0] + xx * 32 + j; ostr = 96;
            }
            float2 acc[8];
#pragma unroll
            for (int nn = 0; nn < 8; nn++) acc[nn] = make_float2(0.f, 0.f);
            for (int c = 0; c < 64; c += 4) {
                float2 w0 = __ldg(wp + (c + 0) * wstr);
                float2 w1 = __ldg(wp + (c + 1) * wstr);
                float2 w2 = __ldg(wp + (c + 2) * wstr);
                float2 w3 = __ldg(wp + (c + 3) * wstr);
                float2 b0 = __ldg(bp + (c + 0) * wstr);
                float2 b1 = __ldg(bp + (c + 1) * wstr);
                float2 b2 = __ldg(bp + (c + 2) * wstr);
                float2 b3 = __ldg(bp + (c + 3) * wstr);
#pragma unroll
                for (int nn = 0; nn < 8; nn++) {
                    float4 u1 = *(const float4*)(in1 + nn * istr + c);
                    float4 u2 = *(const float4*)(in2 + nn * istr + c);
                    acc[nn].x += u1.x * w0.x + u2.x * b0.x;
                    acc[nn].y += u1.x * w0.y + u2.x * b0.y;
                    acc[nn].x += u1.y * w1.x + u2.y * b1.x;
                    acc[nn].y += u1.y * w1.y + u2.y * b1.y;
                    acc[nn].x += u1.z * w2.x + u2.z * b2.x;
                    acc[nn].y += u1.z * w2.y + u2.z * b2.y;
                    acc[nn].x += u1.w * w3.x + u2.w * b3.x;
                    acc[nn].y += u1.w * w3.y + u2.w * b3.y;
                }
            }
#pragma unroll
            for (int nn = 0; nn < 8; nn++) o2[nn * ostr] = acc[nn];
        } else if (wid == 5) {
            int j = tid - 160;
            const float2* wp = (const float2*)(sis + layer * 4096) + j;
            float2 acc[8];
#pragma unroll
            for (int nn = 0; nn < 8; nn++) acc[nn] = make_float2(0.f, 0.f);
            for (int c = 0; c < 64; c += 4) {
                float2 w0 = __ldg(wp + (c + 0) * 32);
                float2 w1 = __ldg(wp + (c + 1) * 32);
                float2 w2 = __ldg(wp + (c + 2) * 32);
                float2 w3 = __ldg(wp + (c + 3) * 32);
#pragma unroll
                for (int nn = 0; nn < 8; nn++) {
                    float4 u = *(const float4*)(&s_ys[nn][c]);
                    acc[nn].x += u.x * w0.x + u.y * w1.x + u.z * w2.x + u.w * w3.x;
                    acc[nn].y += u.x * w0.y + u.y * w1.y + u.z * w2.y + u.w * w3.y;
                }
            }
#pragma unroll
            for (int nn = 0; nn < 8; nn++)
                ((float2*)&s_y2s[0][0])[nn * 32 + j] = acc[nn];
        } else if (tid < 240) {
            int id = tid - 192, xx = id >> 4, j = id & 15;
            const float4* wp = (const float4*)(siv + layer * 4096) + j;
            const float* in = &s_yv[0][xx * 64];
            float4 acc[8];
#pragma unroll
            for (int nn = 0; nn < 8; nn++) acc[nn] = make_float4(0.f, 0.f, 0.f, 0.f);
            for (int c = 0; c < 64; c += 4) {
                float4 w0 = __ldg(wp + (c + 0) * 16);
                float4 w1 = __ldg(wp + (c + 1) * 16);
                float4 w2 = __ldg(wp + (c + 2) * 16);
                float4 w3 = __ldg(wp + (c + 3) * 16);
#pragma unroll
                for (int nn = 0; nn < 8; nn++) {
                    float4 u = *(const float4*)(in + nn * 192 + c);
                    acc[nn].x += u.x * w0.x + u.y * w1.x + u.z * w2.x + u.w * w3.x;
                    acc[nn].y += u.x * w0.y + u.y * w1.y + u.z * w2.y + u.w * w3.y;
                    acc[nn].z += u.x * w0.z + u.y * w1.z + u.z * w2.z + u.w * w3.z;
                    acc[nn].w += u.x * w0.w + u.y * w1.w + u.z * w2.w + u.w * w3.w;
                }
            }
#pragma unroll
            for (int nn = 0; nn < 8; nn++)
                ((float4*)&s_y2v[0][0])[nn * 48 + xx * 16 + j] = acc[nn];
        }
        __syncthreads();
        for (int t = tid; t < 512; t += 256) {
            int node = t >> 6, c = t & 63;
            int n = g_nidx[pbase + node];
            if (n >= 0) {
                float os = s_outs[node][c];
                float gs = os / (1.f + __expf(-os));
                float gate = 1.f / (1.f + __expf(-s_outs[node][64 + c]));
                float yo = ys_new[n * 64 + c];
                float ns = 2.f * s_ys[node][c] - yo + hh * (m * gs + (m - 1.f) * s_y2s[node][c]);
                ys_new[n * 64 + c] = ns;
#pragma unroll
                for (int xx = 0; xx < 3; xx++) {
                    float yov = yv_new[n * 192 + c * 3 + xx];
                    float nv = 2.f * s_yv[node][xx * 64 + c] - yov +
                               hh * (m * gate * s_outv[node][xx * 64 + c] +
                                     (m - 1.f) * s_y2v[node][xx * 64 + c]);
                    yv_new[n * 192 + c * 3 + xx] = nv;
                    s_newv[node][xx * 64 + c] = nv;
                }
            }
        }
        __syncthreads();
        if (tid < 48) {
            int node = tid / 6, r = tid % 6, k = r / 3, xx = r % 3;
            int n = g_nidx[pbase + node];
            if (n >= 0) {
                float acc = 0.f;
#pragma unroll 8
                for (int c = 0; c < 64; c++) acc += s_newv[node][xx * 64 + c] * s_Q[c * 2 + k];
                if (layer == 0) {
                    if (k == 0) g_pos[n * 3 + xx] = acc;
                } else {
                    outp[n * 6 + k * 3 + xx] = acc;
                }
            }
        }
        __syncthreads();
    }
}

// ---------------- launch ----------------
extern "C" void kernel_launch(void* const* d_in, const int* in_sizes, int n_in,
                              void* d_out, int out_size) {
    const float* x        = (const float*)d_in[0];
    const int*   attr     = (const int*)d_in[2];
    const int*   esrc     = (const int*)d_in[3];
    const int*   edst     = (const int*)d_in[4];
    const float* emb      = (const float*)d_in[5];
    const float* uplift   = (const float*)d_in[6];
    const float* h        = (const float*)d_in[7];
    const float* mix      = (const float*)d_in[8];
    const float* rW1      = (const float*)d_in[9];
    const float* rb1      = (const float*)d_in[10];
    const float* rW2      = (const float*)d_in[11];
    const float* lin1s    = (const float*)d_in[12];
    const float* lin1v    = (const float*)d_in[13];
    const float* lin2s    = (const float*)d_in[14];
    const float* lin2v    = (const float*)d_in[15];
    const float* scs      = (const float*)d_in[16];
    const float* scv      = (const float*)d_in[17];
    const float* sis      = (const float*)d_in[18];
    const float* siv      = (const float*)d_in[19];
    float* out = (float*)d_out;

    const int PB = NPAD / 16;  // 1300

    k_init<<<6537, 256>>>(x, uplift, emb, scs, scv, lin1v, attr, esrc, edst); // 0
    k_scan_e<<<1, 512>>>();                                                   // 1
    k_scat_e<<<1280, 256>>>(esrc, edst, x);                                   // 2
    k_edge<<<2000, 256>>>(rW1, rb1, rW2, 0, 1);                               // 3 <- profiled
    k_post<<<PB, 256>>>(lin2s, lin2v, sis, siv, h, mix, 0, 0, out);           // 4
    k_pre<<<NN / 8, 256>>>(lin1s, lin1v, 1, 1);                               // 5 (+cnt cleanup)
    k_edge<<<2000, 256>>>(rW1, rb1, rW2, 1, 0);                               // 6
    k_post<<<PB, 256>>>(lin2s, lin2v, sis, siv, h, mix, 1, 1, out);           // 7
}

// round 16
// speedup vs baseline: 1.1253x; 1.0773x over previous
#include <cuda_runtime.h>
#include <cuda_bf16.h>
#include <math.h>

#define NN 20000
#define NE 640000
#define NL 2
#define MAXR 2.5f
#define INV_NN 0.17677669529663687f   // 1/sqrt(32)
#define NPAD 20800                    // attr-sorted node list padded to 8-aligned segments

// ---------------- scratch (device globals; no allocs) ----------------
static __device__ float g_Q[64 * 2];
static __device__ float g_ys[2][NN * 64];
static __device__ float g_yv[2][NN * 192];
static __device__ float g_s1[NN * 64];
static __device__ float g_v1[NN * 192];          // [n][3][64] x-major
static __device__ float g_agg[NN * 256];         // (n, c, 4): vx,vy,vz,s
static __device__ float g_pos[NN * 3];
// dup-bf16x2 tables (each uint = value duplicated into both bf16 halves)
static __device__ unsigned g_Bsd[NL * 100 * 64 * 128];
static __device__ unsigned g_Bvd[NL * 100 * 64 * 64];
static __device__ unsigned g_wL2s[NL * 64 * 128];
static __device__ unsigned g_wL2v[NL * 64 * 64];
static __device__ unsigned g_wSs[NL * 64 * 64];
static __device__ unsigned g_wSv[NL * 64 * 64];
// edge sort (by dst, filtered); counters zeroed by k_pre of the PREVIOUS call (.bss first)
static __device__ int g_ecnt[NN];
static __device__ int g_eoff[NN];
static __device__ int g_eppos[NN];
static __device__ int g_nesurv;
static __device__ int g_ssrc[NE];
static __device__ int g_sdst[NE];
// node sort (by attr), 8-aligned segments, -1 = sentinel
static __device__ int g_nidx[NPAD];
static __device__ int g_nattr[NPAD];

__device__ __forceinline__ unsigned dupbf(float v) {
    __nv_bfloat162 p = __float2bfloat162_rn(v);
    return *reinterpret_cast<unsigned*>(&p);
}
__device__ __forceinline__ __nv_bfloat162 asbf2(unsigned u) {
    return *reinterpret_cast<__nv_bfloat162*>(&u);
}

// ---- fused init: Q + y init + layer0 v1 + B precompute + weight cvt + sort + hist ----
__global__ void __launch_bounds__(256) k_init(const float* __restrict__ x,
                                              const float* __restrict__ M,
                                              const float* __restrict__ emb,
                                              const float* __restrict__ scs,
                                              const float* __restrict__ scv,
                                              const float* __restrict__ lin1v,
                                              const float* __restrict__ lin2s,
                                              const float* __restrict__ lin2v,
                                              const float* __restrict__ sis,
                                              const float* __restrict__ siv,
                                              const int* __restrict__ attr,
                                              const int* __restrict__ esrc,
                                              const int* __restrict__ edst) {
    int tid = threadIdx.x;
    if (blockIdx.x < 5000) {
        __shared__ double dI[3];
        __shared__ float sQ[128];
        __shared__ float sR[128];
        if (tid < 32) {
            double m0a = M[2 * tid], m1a = M[2 * tid + 1];
            double m0b = M[2 * (tid + 32)], m1b = M[2 * (tid + 32) + 1];
            double pa = m0a * m0a + m0b * m0b;
            double pb = m0a * m1a + m0b * m1b;
            double pc = m1a * m1a + m1b * m1b;
#pragma unroll
            for (int off = 16; off > 0; off >>= 1) {
                pa += __shfl_down_sync(0xffffffffu, pa, off);
                pb += __shfl_down_sync(0xffffffffu, pb, off);
                pc += __shfl_down_sync(0xffffffffu, pc, off);
            }
            if (tid == 0) {
                double det = pa * pc - pb * pb;
                double s = sqrt(det);
                double t = pa + pc;
                double denom = sqrt(t + 2.0 * s);
                double p00 = (pa + s) / denom, p01 = pb / denom, p11 = (pc + s) / denom;
                double pdet = p00 * p11 - p01 * p01;
                dI[0] = p11 / pdet; dI[1] = -p01 / pdet; dI[2] = p00 / pdet;
            }
        }
        __syncthreads();
        if (tid < 64) {
            double m0 = M[2 * tid], m1 = M[2 * tid + 1];
            sQ[2 * tid]     = (float)(m0 * dI[0] + m1 * dI[1]);
            sQ[2 * tid + 1] = (float)(m0 * dI[1] + m1 * dI[2]);
        }
        __syncthreads();
        if (blockIdx.x == 0 && tid < 128) g_Q[tid] = sQ[tid];
        if (tid < 128) {
            int k = tid >> 6, d = tid & 63;
            float acc = 0.f;
#pragma unroll 8
            for (int c = 0; c < 64; c++) acc += sQ[c * 2 + k] * lin1v[c * 64 + d];
            sR[k * 64 + d] = acc;
        }
        __syncthreads();
        int i = blockIdx.x * 256 + tid;
        if (i >= NN * 64) return;
        int n = i >> 6, c = i & 63;
        float q0 = sQ[c * 2], q1 = sQ[c * 2 + 1];
        const float* xp = x + n * 6;
        float v0 = xp[0] * q0 + xp[3] * q1;
        float v1 = xp[1] * q0 + xp[4] * q1;
        float v2 = xp[2] * q0 + xp[5] * q1;
        int base = n * 192 + c * 3;
        g_yv[0][base + 0] = v0; g_yv[0][base + 1] = v1; g_yv[0][base + 2] = v2;
        g_yv[1][base + 0] = v0; g_yv[1][base + 1] = v1; g_yv[1][base + 2] = v2;
        g_ys[0][i] = 0.f; g_ys[1][i] = 0.f;
        if (c < 3) g_pos[n * 3 + c] = xp[c];
        reinterpret_cast<float4*>(g_agg)[i] = make_float4(0.f, 0.f, 0.f, 0.f);
        int d = c;
        float r0 = sR[d], r1 = sR[64 + d];
#pragma unroll
        for (int xx = 0; xx < 3; xx++)
            g_v1[n * 192 + xx * 64 + d] = xp[xx] * r0 + xp[3 + xx] * r1;
    } else if (blockIdx.x < 5256) {
        // ---- B precompute, tiled (writes dup-bf16x2) ----
        int b = blockIdx.x - 5000;
        __shared__ __align__(16) float semb[3200];
        for (int i = tid; i < 3200; i += 256) semb[i] = emb[i];
        __syncthreads();
        if (b < 128) {
            int l = b >> 6, c = b & 63;
            int o = tid & 127, ah = tid >> 7;
            float wcol[32];
            const float* w = scs + ((size_t)(l * 64 + c) * 32) * 128 + o;
#pragma unroll
            for (int e2 = 0; e2 < 32; e2++) wcol[e2] = w[e2 * 128];
            int a0 = ah * 50, a1 = a0 + 50;
            for (int a = a0; a < a1; a++) {
                const float4* em = (const float4*)(semb + a * 32);
                float acc = 0.f;
#pragma unroll
                for (int e4 = 0; e4 < 8; e4++) {
                    float4 u = em[e4];
                    acc += u.x * wcol[e4 * 4] + u.y * wcol[e4 * 4 + 1] +
                           u.z * wcol[e4 * 4 + 2] + u.w * wcol[e4 * 4 + 3];
                }
                g_Bsd[((size_t)(l * 100 + a) * 64 + c) * 128 + o] = dupbf(acc);
            }
        } else {
            int b2 = b - 128;
            int l = b2 >> 6, c = b2 & 63;
            int o = tid & 63, ah = tid >> 6;
            float wcol[32];
            const float* w = scv + ((size_t)(l * 64 + c) * 32) * 64 + o;
#pragma unroll
            for (int e2 = 0; e2 < 32; e2++) wcol[e2] = w[e2 * 64];
            int a0 = ah * 25, a1 = a0 + 25;
            for (int a = a0; a < a1; a++) {
                const float4* em = (const float4*)(semb + a * 32);
                float acc = 0.f;
#pragma unroll
                for (int e4 = 0; e4 < 8; e4++) {
                    float4 u = em[e4];
                    acc += u.x * wcol[e4 * 4] + u.y * wcol[e4 * 4 + 1] +
                           u.z * wcol[e4 * 4 + 2] + u.w * wcol[e4 * 4 + 3];
                }
                g_Bvd[((size_t)(l * 100 + a) * 64 + c) * 64 + o] = dupbf(acc);
            }
        }
    } else if (blockIdx.x == 5256) {
        // single-block node counting sort by attr, segments padded to 8
        __shared__ int scnt[128], soff[128], spos[128];
        if (tid < 128) { scnt[tid] = 0; spos[tid] = 0; }
        __syncthreads();
        for (int n = tid; n < NN; n += 256) atomicAdd(&scnt[attr[n]], 1);
        __syncthreads();
        int pc = 0;
        if (tid < 128) { pc = (scnt[tid] + 7) & ~7; soff[tid] = pc; }
        __syncthreads();
        for (int off = 1; off < 128; off <<= 1) {
            int v = 0;
            if (tid < 128 && tid >= off) v = soff[tid - off];
            __syncthreads();
            if (tid < 128) soff[tid] += v;
            __syncthreads();
        }
        if (tid < 128) soff[tid] -= pc;
        __syncthreads();
        for (int i = tid; i < NPAD; i += 256) g_nidx[i] = -1;
        __syncthreads();
        for (int n = tid; n < NN; n += 256) {
            int a = attr[n];
            int p = soff[a] + atomicAdd(&spos[a], 1);
            g_nidx[p] = n;
            g_nattr[p] = a;
        }
    } else if (blockIdx.x < 5273) {
        // weight conversion to dup-bf16x2 (16 blocks, 40960 elements)
        const int T1 = NL * 8192, T2 = T1 + NL * 4096, T3 = T2 + NL * 4096, T4 = T3 + NL * 4096;
        for (int i = (blockIdx.x - 5257) * 256 + tid; i < T4; i += 16 * 256) {
            if (i < T1) g_wL2s[i] = dupbf(lin2s[i]);
            else if (i < T2) g_wL2v[i - T1] = dupbf(lin2v[i - T1]);
            else if (i < T3) g_wSs[i - T2] = dupbf(sis[i - T2]);
            else g_wSv[i - T3] = dupbf(siv[i - T3]);
        }
    } else {
        // FILTERED edge histogram (layer-0 positions = x)
        for (int e = (blockIdx.x - 5273) * 256 + tid; e < NE; e += 1280 * 256) {
            int s = esrc[e], d = edst[e];
            float dx = x[s * 6 + 0] - x[d * 6 + 0];
            float dy = x[s * 6 + 1] - x[d * 6 + 1];
            float dz = x[s * 6 + 2] - x[d * 6 + 2];
            if (dx * dx + dy * dy + dz * dz < MAXR * MAXR)
                atomicAdd(&g_ecnt[d], 1);
        }
    }
}

// ---------------- edge offset scan (writes surviving count) ----------------
__global__ void __launch_bounds__(512) k_scan_e() {
    __shared__ int sp[512];
    int t = threadIdx.x;
    const int CH = 40;
    int base = t * CH;
    int part = 0;
    for (int i = 0; i < CH; i++) {
        int idx = base + i;
        if (idx < NN) part += g_ecnt[idx];
    }
    sp[t] = part;
    __syncthreads();
    for (int off = 1; off < 512; off <<= 1) {
        int v = (t >= off) ? sp[t - off] : 0;
        __syncthreads();
        sp[t] += v;
        __syncthreads();
    }
    if (t == 511) g_nesurv = sp[511];
    int run = sp[t] - part;
    for (int i = 0; i < CH; i++) {
        int idx = base + i;
        if (idx < NN) { g_eoff[idx] = run; run += g_ecnt[idx]; }
    }
}

// ---------------- filtered edge scatter ----------------
__global__ void k_scat_e(const int* __restrict__ esrc, const int* __restrict__ edst,
                         const float* __restrict__ x) {
    for (int e = blockIdx.x * 256 + threadIdx.x; e < NE; e += 1280 * 256) {
        int s = esrc[e], d = edst[e];
        float dx = x[s * 6 + 0] - x[d * 6 + 0];
        float dy = x[s * 6 + 1] - x[d * 6 + 1];
        float dz = x[s * 6 + 2] - x[d * 6 + 2];
        if (dx * dx + dy * dy + dz * dz < MAXR * MAXR) {
            int p = g_eoff[d] + atomicAdd(&g_eppos[d], 1);
            g_ssrc[p] = s;
            g_sdst[p] = d;
        }
    }
}

// ------- pre (layer 1) + sort-counter cleanup for next call's hist -------
__global__ void __launch_bounds__(256) k_pre(const float* __restrict__ lin1s,
                                             const float* __restrict__ lin1v,
                                             int layer, int cur) {
    __shared__ float sWs[4096], sWv[4096];
    __shared__ float sy[8][256];
    int tid = threadIdx.x;
    {
        int i = blockIdx.x * 256 + tid;
        if (i < NN) { g_ecnt[i] = 0; g_eppos[i] = 0; }
    }
    const float* Ws = lin1s + layer * 4096;
    const float* Wv = lin1v + layer * 4096;
    for (int k = tid; k < 4096; k += 256) { sWs[k] = Ws[k]; sWv[k] = Wv[k]; }
    const float* ys = g_ys[cur];
    const float* yv = g_yv[cur];
    int n0 = blockIdx.x * 8;
    for (int k = tid; k < 2048; k += 256) {
        int nn = k >> 8, j = k & 255;
        int n = n0 + nn;
        sy[nn][j] = (j < 64) ? ys[n * 64 + j] : yv[n * 192 + j - 64];
    }
    __syncthreads();
    for (int nn = 0; nn < 8; nn++) {
        int n = n0 + nn;
        if (tid < 64) {
            int d = tid;
            float acc = 0.f;
#pragma unroll 8
            for (int c = 0; c < 64; c++) acc += sy[nn][c] * sWs[c * 64 + d];
            g_s1[n * 64 + d] = acc;
        } else {
            int idx = tid - 64;
            int d = idx & 63, xx = idx >> 6;
            float acc = 0.f;
#pragma unroll 8
            for (int c = 0; c < 64; c++) acc += sy[nn][64 + c * 3 + xx] * sWv[c * 64 + d];
            g_v1[n * 192 + xx * 64 + d] = acc;
        }
    }
}

// -------- per-edge scalar math (W1 in regs); cut = sin^2(th) identity --------
__device__ __forceinline__ float edge_scalar(float ev0, float ev1, float ev2, float l2,
                                             const float* w1r, float br,
                                             float& ea0, float& ea1, float& ea2) {
    const float PI = 3.14159265358979f;
    float elen = sqrtf(l2);
    float safe = fmaxf(elen, 1e-9f);
    float inv = 1.0f / safe;
    float th = (PI / MAXR) * safe;
    float sk = __sinf(th), c2 = 2.f * __cosf(th);
    float ca = sk * sk * 1.7320508075688772f * inv;
    ea0 = ca * ev0; ea1 = ca * ev1; ea2 = ca * ev2;
    float skm1 = 0.f, skk = sk;
    float fac = 2.5298221281347035f * inv;
    float hs = br;
#pragma unroll
    for (int k = 0; k < 8; k++) {
        hs += (fac * skk) * w1r[k];
        float t = c2 * skk - skm1; skm1 = skk; skk = t;
    }
    return hs / (1.f + __expf(-hs));  // silu
}

// W2 duplicated-bf16x2 layout: sW2d[k*32+lane] = {dup(w0),dup(w1),dup(w2),dup(w3)}
__device__ __forceinline__ void fill_w2d(uint4* sW2d, const float* rW2, int layer,
                                         int tid) {
    for (int t = tid; t < 1024; t += 256) {
        int k = t >> 5, ln = t & 31;
        const float* base = rW2 + layer * 4096 + k * 128;
        uint4 v;
        v.x = dupbf(base[ln]);
        v.y = dupbf(base[32 + ln]);
        v.z = dupbf(base[64 + ln]);
        v.w = dupbf(base[96 + ln]);
        sW2d[t] = v;
    }
}

// -------- edge: dst-sorted filtered list, 4-edge groups (natural regs) --------
__global__ void __launch_bounds__(256) k_edge(const float* __restrict__ rW1,
                                              const float* __restrict__ rb1,
                                              const float* __restrict__ rW2,
                                              int layer, int skip_s1) {
    __shared__ uint4 sW2d[1024];   // 16 KB
    int tid = threadIdx.x;
    int lane = tid & 31;
    fill_w2d(sW2d, rW2, layer, tid);
    float w1r[8];
#pragma unroll
    for (int k = 0; k < 8; k++) w1r[k] = rW1[layer * 256 + k * 32 + lane];
    float br = rb1[layer * 32 + lane];
    __syncthreads();
    int cnt = g_nesurv;
    int warp = (blockIdx.x * 256 + tid) >> 5;
    int nw = gridDim.x * 8;
    int K = (cnt + nw - 1) / nw;
    int e0 = warp * K;
    if (e0 >= cnt) return;
    int e1 = e0 + K; if (e1 > cnt) e1 = cnt;
    float4 acc0 = make_float4(0.f, 0.f, 0.f, 0.f);
    float4 acc1 = make_float4(0.f, 0.f, 0.f, 0.f);
    bool touched = false;
    int cur = -1;
    __nv_bfloat162 zz; zz.x = __float2bfloat16(0.f); zz.y = zz.x;
    for (int e = e0; e < e1; e += 4) {
        int cnt4 = e1 - e; if (cnt4 > 4) cnt4 = 4;
        int srcs[4], dsts[4];
        float hv4[4], eaX[4], eaY[4], eaZ[4];
#pragma unroll
        for (int i = 0; i < 4; i++) {
            int idx = (i < cnt4) ? (e + i) : (e + cnt4 - 1);
            int d = g_sdst[idx], s = g_ssrc[idx];
            srcs[i] = s; dsts[i] = d;
            float dp0 = g_pos[d * 3 + 0], dp1 = g_pos[d * 3 + 1], dp2 = g_pos[d * 3 + 2];
            float ev0 = g_pos[s * 3 + 0] - dp0;
            float ev1 = g_pos[s * 3 + 1] - dp1;
            float ev2 = g_pos[s * 3 + 2] - dp2;
            float l2 = ev0 * ev0 + ev1 * ev1 + ev2 * ev2;
            float h = edge_scalar(ev0, ev1, ev2, l2, w1r, br, eaX[i], eaY[i], eaZ[i]);
            hv4[i] = (i < cnt4) ? h : 0.f;
        }
        __nv_bfloat162 h01 = __floats2bfloat162_rn(hv4[0], hv4[1]);
        __nv_bfloat162 h23 = __floats2bfloat162_rn(hv4[2], hv4[3]);
        unsigned u01 = *reinterpret_cast<unsigned*>(&h01);
        unsigned u23 = *reinterpret_cast<unsigned*>(&h23);
        __nv_bfloat162 p0 = zz, p1 = zz, p2 = zz, p3 = zz;
        __nv_bfloat162 q0 = zz, q1 = zz, q2 = zz, q3 = zz;
#pragma unroll
        for (int k = 0; k < 32; k++) {
            unsigned s01 = __shfl_sync(0xffffffffu, u01, k);
            unsigned s23 = __shfl_sync(0xffffffffu, u23, k);
            uint4 wv = sW2d[k * 32 + lane];
            __nv_bfloat162 b01 = asbf2(s01);
            __nv_bfloat162 b23 = asbf2(s23);
            p0 = __hfma2(b01, asbf2(wv.x), p0);
            p1 = __hfma2(b01, asbf2(wv.y), p1);
            p2 = __hfma2(b01, asbf2(wv.z), p2);
            p3 = __hfma2(b01, asbf2(wv.w), p3);
            q0 = __hfma2(b23, asbf2(wv.x), q0);
            q1 = __hfma2(b23, asbf2(wv.y), q1);
            q2 = __hfma2(b23, asbf2(wv.z), q2);
            q3 = __hfma2(b23, asbf2(wv.w), q3);
        }
        float2 f0p = __bfloat1622float2(p0), f1p = __bfloat1622float2(p1);
        float2 f2p = __bfloat1622float2(p2), f3p = __bfloat1622float2(p3);
        float2 f0q = __bfloat1622float2(q0), f1q = __bfloat1622float2(q1);
        float2 f2q = __bfloat1622float2(q2), f3q = __bfloat1622float2(q3);
        float w0v[4] = {f0p.x, f0p.y, f0q.x, f0q.y};
        float w1v[4] = {f1p.x, f1p.y, f1q.x, f1q.y};
        float w2v[4] = {f2p.x, f2p.y, f2q.x, f2q.y};
        float w3v[4] = {f3p.x, f3p.y, f3q.x, f3q.y};
#pragma unroll
        for (int i = 0; i < 4; i++) {
            int dst = dsts[i];
            if (dst != cur) {
                if (touched) {
                    float4* ap = reinterpret_cast<float4*>(g_agg + (size_t)cur * 256);
                    atomicAdd(ap + lane, acc0);
                    atomicAdd(ap + lane + 32, acc1);
                    acc0 = make_float4(0.f, 0.f, 0.f, 0.f);
                    acc1 = make_float4(0.f, 0.f, 0.f, 0.f);
                    touched = false;
                }
                cur = dst;
            }
            int src = srcs[i];
            float sa = 0.f, sb = 0.f;
            if (!skip_s1) {
                const float* s1p = g_s1 + (size_t)src * 64;
                sa = s1p[lane] * w0v[i];
                sb = s1p[lane + 32] * w1v[i];
            }
            const float* v1p = g_v1 + (size_t)src * 192;
            float ex = eaX[i], ey = eaY[i], ez = eaZ[i];
            float da = w2v[i] * (v1p[lane] * ex + v1p[64 + lane] * ey + v1p[128 + lane] * ez);
            float db = w3v[i] * (v1p[lane + 32] * ex + v1p[96 + lane] * ey + v1p[160 + lane] * ez);
            acc0.x += sa * ex; acc0.y += sa * ey; acc0.z += sa * ez; acc0.w += da;
            acc1.x += sb * ex; acc1.y += sb * ey; acc1.z += sb * ez; acc1.w += db;
            touched = true;
        }
    }
    if (touched) {
        float4* ap = reinterpret_cast<float4*>(g_agg + (size_t)cur * 256);
        atomicAdd(ap + lane, acc0);
        atomicAdd(ap + lane + 32, acc1);
    }
}

// ------ post v9: node-pair bf16x2 HFMA2 matvec ------
__global__ void __launch_bounds__(256, 4) k_post(const float* __restrict__ hv,
                                                 const float* __restrict__ mv,
                                                 int layer, int cur,
                                                 float* __restrict__ outp) {
    __shared__ float s_Q[128];
    __shared__ __align__(16) float s_ys[8][64], s_aggs[8][64];
    __shared__ __align__(16) float s_yv[8][192], s_aggv[8][192];   // [xx*64+c]
    __shared__ __align__(16) unsigned sPa[256], sPy[256];          // [c*4+p]
    __shared__ __align__(16) unsigned sPav[768], sPyv[768];        // [(xx*64+c)*4+p]
    __shared__ __align__(16) unsigned s_outs_p[512];               // [j*4+p], j<128
    __shared__ __align__(16) unsigned s_y2s_p[256];                // [j*4+p], j<64
    __shared__ __align__(16) unsigned s_outv_p[768];               // [(xx*64+j)*4+p]
    __shared__ __align__(16) unsigned s_y2v_p[768];
    __shared__ float s_newv[8][192];
    int tid = threadIdx.x;
    if (tid < 128) s_Q[tid] = g_Q[tid];
    float hh = hv[layer] * hv[layer];
    float m = mv[layer];
    float* ys_new = g_ys[cur ^ 1];
    float* yv_new = g_yv[cur ^ 1];
    const float* ys_cur = g_ys[cur];
    const float* yv_cur = g_yv[cur];
    __nv_bfloat162 zz; zz.x = __float2bfloat16(0.f); zz.y = zz.x;
    for (int it = 0; it < 2; it++) {
        int pbase = blockIdx.x * 16 + it * 8;
        // ---- stage unpacked ----
        for (int t = tid; t < 512; t += 256) {
            int node = t >> 6, j = t & 63;
            int n = g_nidx[pbase + node];
            if (n >= 0) {
                s_ys[node][j] = ys_cur[n * 64 + j];
                float4 a4 = ((const float4*)g_agg)[n * 64 + j];
                if (layer == 0)
                    ((float4*)g_agg)[n * 64 + j] = make_float4(0.f, 0.f, 0.f, 0.f);
                s_aggs[node][j] = a4.w * INV_NN;
                s_aggv[node][j] = a4.x * INV_NN;
                s_aggv[node][64 + j] = a4.y * INV_NN;
                s_aggv[node][128 + j] = a4.z * INV_NN;
                const float* yvp = yv_cur + n * 192 + j * 3;
                s_yv[node][j] = yvp[0];
                s_yv[node][64 + j] = yvp[1];
                s_yv[node][128 + j] = yvp[2];
            } else {
                s_ys[node][j] = 0.f; s_aggs[node][j] = 0.f;
                s_aggv[node][j] = 0.f; s_aggv[node][64 + j] = 0.f; s_aggv[node][128 + j] = 0.f;
                s_yv[node][j] = 0.f; s_yv[node][64 + j] = 0.f; s_yv[node][128 + j] = 0.f;
            }
        }
        __syncthreads();
        // ---- pack node pairs to bf16x2 ----
        for (int i = tid; i < 2048; i += 256) {
            unsigned v;
            if (i < 256) {
                int c = i >> 2, p = i & 3;
                v = *(unsigned*)&(__nv_bfloat162&)(*(__nv_bfloat162*)0);  // placeholder avoided below
                __nv_bfloat162 pk = __floats2bfloat162_rn(s_aggs[2 * p][c], s_aggs[2 * p + 1][c]);
                v = *reinterpret_cast<unsigned*>(&pk);
                sPa[i] = v;
            } else if (i < 512) {
                int r = i - 256, c = r >> 2, p = r & 3;
                __nv_bfloat162 pk = __floats2bfloat162_rn(s_ys[2 * p][c], s_ys[2 * p + 1][c]);
                sPy[r] = *reinterpret_cast<unsigned*>(&pk);
            } else if (i < 1280) {
                int r = i - 512, cc = r >> 2, p = r & 3;   // cc = xx*64+c
                __nv_bfloat162 pk = __floats2bfloat162_rn(s_aggv[2 * p][cc], s_aggv[2 * p + 1][cc]);
                sPav[r] = *reinterpret_cast<unsigned*>(&pk);
            } else {
                int r = i - 1280, cc = r >> 2, p = r & 3;
                __nv_bfloat162 pk = __floats2bfloat162_rn(s_yv[2 * p][cc], s_yv[2 * p + 1][cc]);
                sPyv[r] = *reinterpret_cast<unsigned*>(&pk);
            }
        }
        __syncthreads();
        int a = g_nattr[pbase];
        // ---- matvec (bf16x2 node pairs) ----
        if (tid < 64) {
            int j2 = tid;
            const uint2* wp = (const uint2*)(g_wL2s + layer * 8192) + j2;
            const uint2* bp = (const uint2*)(g_Bsd + (size_t)(layer * 100 + a) * 8192) + j2;
            bool doY = (j2 < 32);
            const uint2* sp = (const uint2*)(g_wSs + layer * 4096) + j2;
            __nv_bfloat162 aA0[4], aA1[4], aY0[4], aY1[4];
#pragma unroll
            for (int p = 0; p < 4; p++) { aA0[p] = zz; aA1[p] = zz; aY0[p] = zz; aY1[p] = zz; }
            for (int c = 0; c < 64; c++) {
                uint4 A = ((const uint4*)sPa)[c];
                uint4 Y = ((const uint4*)sPy)[c];
                uint2 w = __ldg(wp + c * 64);
                uint2 b = __ldg(bp + c * 64);
                __nv_bfloat162 wx = asbf2(w.x), wy = asbf2(w.y);
                __nv_bfloat162 bx = asbf2(b.x), by = asbf2(b.y);
                __nv_bfloat162 Ab[4] = {asbf2(A.x), asbf2(A.y), asbf2(A.z), asbf2(A.w)};
                __nv_bfloat162 Yb[4] = {asbf2(Y.x), asbf2(Y.y), asbf2(Y.z), asbf2(Y.w)};
#pragma unroll
                for (int p = 0; p < 4; p++) {
                    aA0[p] = __hfma2(wx, Ab[p], aA0[p]);
                    aA0[p] = __hfma2(bx, Yb[p], aA0[p]);
                    aA1[p] = __hfma2(wy, Ab[p], aA1[p]);
                    aA1[p] = __hfma2(by, Yb[p], aA1[p]);
                }
                if (doY) {
                    uint2 s = __ldg(sp + c * 32);
                    __nv_bfloat162 sx = asbf2(s.x), sy2 = asbf2(s.y);
#pragma unroll
                    for (int p = 0; p < 4; p++) {
                        aY0[p] = __hfma2(sx, Yb[p], aY0[p]);
                        aY1[p] = __hfma2(sy2, Yb[p], aY1[p]);
                    }
                }
            }
#pragma unroll
            for (int p = 0; p < 4; p++) {
                s_outs_p[(2 * j2 + 0) * 4 + p] = *reinterpret_cast<unsigned*>(&aA0[p]);
                s_outs_p[(2 * j2 + 1) * 4 + p] = *reinterpret_cast<unsigned*>(&aA1[p]);
            }
            if (doY) {
#pragma unroll
                for (int p = 0; p < 4; p++) {
                    s_y2s_p[(2 * j2 + 0) * 4 + p] = *reinterpret_cast<unsigned*>(&aY0[p]);
                    s_y2s_p[(2 * j2 + 1) * 4 + p] = *reinterpret_cast<unsigned*>(&aY1[p]);
                }
            }
        } else if (tid < 160) {
            int id = tid - 64, xx = id >> 5, j2 = id & 31;
            const uint2* wp = (const uint2*)(g_wL2v + layer * 4096) + j2;
            const uint2* bp = (const uint2*)(g_Bvd + (size_t)(layer * 100 + a) * 4096) + j2;
            __nv_bfloat162 a0[4], a1[4];
#pragma unroll
            for (int p = 0; p < 4; p++) { a0[p] = zz; a1[p] = zz; }
            for (int c = 0; c < 64; c++) {
                uint4 A = ((const uint4*)sPav)[xx * 64 + c];
                uint4 Y = ((const uint4*)sPyv)[xx * 64 + c];
                uint2 w = __ldg(wp + c * 32);
                uint2 b = __ldg(bp + c * 32);
                __nv_bfloat162 wx = asbf2(w.x), wy = asbf2(w.y);
                __nv_bfloat162 bx = asbf2(b.x), by = asbf2(b.y);
                __nv_bfloat162 Ab[4] = {asbf2(A.x), asbf2(A.y), asbf2(A.z), asbf2(A.w)};
                __nv_bfloat162 Yb[4] = {asbf2(Y.x), asbf2(Y.y), asbf2(Y.z), asbf2(Y.w)};
#pragma unroll
                for (int p = 0; p < 4; p++) {
                    a0[p] = __hfma2(wx, Ab[p], a0[p]);
                    a0[p] = __hfma2(bx, Yb[p], a0[p]);
                    a1[p] = __hfma2(wy, Ab[p], a1[p]);
                    a1[p] = __hfma2(by, Yb[p], a1[p]);
                }
            }
#pragma unroll
            for (int p = 0; p < 4; p++) {
                s_outv_p[(xx * 64 + 2 * j2 + 0) * 4 + p] = *reinterpret_cast<unsigned*>(&a0[p]);
                s_outv_p[(xx * 64 + 2 * j2 + 1) * 4 + p] = *reinterpret_cast<unsigned*>(&a1[p]);
            }
        } else {
            int id = tid - 160, xx = id / 32, j2 = id % 32;
            const uint2* sp = (const uint2*)(g_wSv + layer * 4096) + j2;
            __nv_bfloat162 a0[4], a1[4];
#pragma unroll
            for (int p = 0; p < 4; p++) { a0[p] = zz; a1[p] = zz; }
            for (int c = 0; c < 64; c++) {
                uint4 Y = ((const uint4*)sPyv)[xx * 64 + c];
                uint2 s = __ldg(sp + c * 32);
                __nv_bfloat162 sx = asbf2(s.x), sy2 = asbf2(s.y);
                __nv_bfloat162 Yb[4] = {asbf2(Y.x), asbf2(Y.y), asbf2(Y.z), asbf2(Y.w)};
#pragma unroll
                for (int p = 0; p < 4; p++) {
                    a0[p] = __hfma2(sx, Yb[p], a0[p]);
                    a1[p] = __hfma2(sy2, Yb[p], a1[p]);
                }
            }
#pragma unroll
            for (int p = 0; p < 4; p++) {
                s_y2v_p[(xx * 64 + 2 * j2 + 0) * 4 + p] = *reinterpret_cast<unsigned*>(&a0[p]);
                s_y2v_p[(xx * 64 + 2 * j2 + 1) * 4 + p] = *reinterpret_cast<unsigned*>(&a1[p]);
            }
        }
        __syncthreads();
        // ---- state update (unpack bf16x2 by node parity) ----
        for (int t = tid; t < 512; t += 256) {
            int node = t >> 6, c = t & 63;
            int n = g_nidx[pbase + node];
            if (n >= 0) {
                int p = node >> 1, hi = node & 1;
                float2 vos = __bfloat1622float2(asbf2(s_outs_p[c * 4 + p]));
                float2 vgt = __bfloat1622float2(asbf2(s_outs_p[(64 + c) * 4 + p]));
                float2 vy2 = __bfloat1622float2(asbf2(s_y2s_p[c * 4 + p]));
                float os = hi ? vos.y : vos.x;
                float gt = hi ? vgt.y : vgt.x;
                float y2 = hi ? vy2.y : vy2.x;
                float gs = os / (1.f + __expf(-os));
                float gate = 1.f / (1.f + __expf(-gt));
                float yo = ys_new[n * 64 + c];
                float ns = 2.f * s_ys[node][c] - yo + hh * (m * gs + (m - 1.f) * y2);
                ys_new[n * 64 + c] = ns;
#pragma unroll
                for (int xx = 0; xx < 3; xx++) {
                    float2 vov = __bfloat1622float2(asbf2(s_outv_p[(xx * 64 + c) * 4 + p]));
                    float2 vyv = __bfloat1622float2(asbf2(s_y2v_p[(xx * 64 + c) * 4 + p]));
                    float ov = hi ? vov.y : vov.x;
                    float yv2 = hi ? vyv.y : vyv.x;
                    float yov = yv_new[n * 192 + c * 3 + xx];
                    float nv = 2.f * s_yv[node][xx * 64 + c] - yov +
                               hh * (m * gate * ov + (m - 1.f) * yv2);
                    yv_new[n * 192 + c * 3 + xx] = nv;
                    s_newv[node][xx * 64 + c] = nv;
                }
            }
        }
        __syncthreads();
        // ---- projection ----
        if (tid < 48) {
            int node = tid / 6, r = tid % 6, k = r / 3, xx = r % 3;
            int n = g_nidx[pbase + node];
            if (n >= 0) {
                float acc = 0.f;
#pragma unroll 8
                for (int c = 0; c < 64; c++) acc += s_newv[node][xx * 64 + c] * s_Q[c * 2 + k];
                if (layer == 0) {
                    if (k == 0) g_pos[n * 3 + xx] = acc;
                } else {
                    outp[n * 6 + k * 3 + xx] = acc;
                }
            }
        }
        __syncthreads();
    }
}

// ---------------- launch ----------------
extern "C" void kernel_launch(void* const* d_in, const int* in_sizes, int n_in,
                              void* d_out, int out_size) {
    const float* x        = (const float*)d_in[0];
    const int*   attr     = (const int*)d_in[2];
    const int*   esrc     = (const int*)d_in[3];
    const int*   edst     = (const int*)d_in[4];
    const float* emb      = (const float*)d_in[5];
    const float* uplift   = (const float*)d_in[6];
    const float* h        = (const float*)d_in[7];
    const float* mix      = (const float*)d_in[8];
    const float* rW1      = (const float*)d_in[9];
    const float* rb1      = (const float*)d_in[10];
    const float* rW2      = (const float*)d_in[11];
    const float* lin1s    = (const float*)d_in[12];
    const float* lin1v    = (const float*)d_in[13];
    const float* lin2s    = (const float*)d_in[14];
    const float* lin2v    = (const float*)d_in[15];
    const float* scs      = (const float*)d_in[16];
    const float* scv      = (const float*)d_in[17];
    const float* sis      = (const float*)d_in[18];
    const float* siv      = (const float*)d_in[19];
    float* out = (float*)d_out;

    const int PB = NPAD / 16;  // 1300

    k_init<<<6553, 256>>>(x, uplift, emb, scs, scv, lin1v, lin2s, lin2v, sis, siv,
                          attr, esrc, edst);                                   // 0
    k_scan_e<<<1, 512>>>();                                                    // 1
    k_scat_e<<<1280, 256>>>(esrc, edst, x);                                    // 2
    k_edge<<<2000, 256>>>(rW1, rb1, rW2, 0, 1);                                // 3 <- profiled
    k_post<<<PB, 256>>>(h, mix, 0, 0, out);                                    // 4
    k_pre<<<NN / 8, 256>>>(lin1s, lin1v, 1, 1);                                // 5 (+cnt cleanup)
    k_edge<<<2000, 256>>>(rW1, rb1, rW2, 1, 0);                                // 6
    k_post<<<PB, 256>>>(h, mix, 1, 1, out);                                    // 7
}

// round 17
// speedup vs baseline: 1.2096x; 1.0749x over previous
#include <cuda_runtime.h>
#include <cuda_bf16.h>
#include <math.h>

#define NN 20000
#define NE 640000
#define NL 2
#define MAXR 2.5f
#define INV_NN 0.17677669529663687f   // 1/sqrt(32)
#define NPAD 20800                    // attr-sorted node list padded to 8-aligned segments

// ---------------- scratch (device globals; no allocs) ----------------
static __device__ float g_Q[64 * 2];
static __device__ float g_ys[2][NN * 64];
static __device__ float g_yv[2][NN * 192];
static __device__ float g_s1[NN * 64];
static __device__ float g_v1[NN * 192];          // [n][3][64] x-major
static __device__ float g_agg[NN * 256];         // (n, c, 4): vx,vy,vz,s
static __device__ float g_pos[NN * 3];
// dup-bf16x2 tables (each uint = value duplicated into both bf16 halves)
static __device__ unsigned g_Bsd[NL * 100 * 64 * 128];
static __device__ unsigned g_Bvd[NL * 100 * 64 * 64];
static __device__ unsigned g_wL2s[NL * 64 * 128];
static __device__ unsigned g_wL2v[NL * 64 * 64];
static __device__ unsigned g_wSs[NL * 64 * 64];
static __device__ unsigned g_wSv[NL * 64 * 64];
// edge sort (by dst, filtered); counters zeroed by k_pre of the PREVIOUS call (.bss first)
static __device__ int g_ecnt[NN];
static __device__ int g_eoff[NN];
static __device__ int g_eppos[NN];
static __device__ int g_nesurv;
static __device__ int g_ssrc[NE];
static __device__ int g_sdst[NE];
// node sort (by attr), 8-aligned segments, -1 = sentinel
static __device__ int g_nidx[NPAD];
static __device__ int g_nattr[NPAD];

__device__ __forceinline__ unsigned dupbf(float v) {
    __nv_bfloat162 p = __float2bfloat162_rn(v);
    return *reinterpret_cast<unsigned*>(&p);
}
__device__ __forceinline__ __nv_bfloat162 asbf2(unsigned u) {
    return *reinterpret_cast<__nv_bfloat162*>(&u);
}

// ---- fused init: Q + y init + layer0 v1 + B precompute + weight cvt + sort + hist ----
__global__ void __launch_bounds__(256) k_init(const float* __restrict__ x,
                                              const float* __restrict__ M,
                                              const float* __restrict__ emb,
                                              const float* __restrict__ scs,
                                              const float* __restrict__ scv,
                                              const float* __restrict__ lin1v,
                                              const float* __restrict__ lin2s,
                                              const float* __restrict__ lin2v,
                                              const float* __restrict__ sis,
                                              const float* __restrict__ siv,
                                              const int* __restrict__ attr,
                                              const int* __restrict__ esrc,
                                              const int* __restrict__ edst) {
    int tid = threadIdx.x;
    if (blockIdx.x < 5000) {
        __shared__ double dI[3];
        __shared__ float sQ[128];
        __shared__ float sR[128];
        if (tid < 32) {
            double m0a = M[2 * tid], m1a = M[2 * tid + 1];
            double m0b = M[2 * (tid + 32)], m1b = M[2 * (tid + 32) + 1];
            double pa = m0a * m0a + m0b * m0b;
            double pb = m0a * m1a + m0b * m1b;
            double pc = m1a * m1a + m1b * m1b;
#pragma unroll
            for (int off = 16; off > 0; off >>= 1) {
                pa += __shfl_down_sync(0xffffffffu, pa, off);
                pb += __shfl_down_sync(0xffffffffu, pb, off);
                pc += __shfl_down_sync(0xffffffffu, pc, off);
            }
            if (tid == 0) {
                double det = pa * pc - pb * pb;
                double s = sqrt(det);
                double t = pa + pc;
                double denom = sqrt(t + 2.0 * s);
                double p00 = (pa + s) / denom, p01 = pb / denom, p11 = (pc + s) / denom;
                double pdet = p00 * p11 - p01 * p01;
                dI[0] = p11 / pdet; dI[1] = -p01 / pdet; dI[2] = p00 / pdet;
            }
        }
        __syncthreads();
        if (tid < 64) {
            double m0 = M[2 * tid], m1 = M[2 * tid + 1];
            sQ[2 * tid]     = (float)(m0 * dI[0] + m1 * dI[1]);
            sQ[2 * tid + 1] = (float)(m0 * dI[1] + m1 * dI[2]);
        }
        __syncthreads();
        if (blockIdx.x == 0 && tid < 128) g_Q[tid] = sQ[tid];
        if (tid < 128) {
            int k = tid >> 6, d = tid & 63;
            float acc = 0.f;
#pragma unroll 8
            for (int c = 0; c < 64; c++) acc += sQ[c * 2 + k] * lin1v[c * 64 + d];
            sR[k * 64 + d] = acc;
        }
        __syncthreads();
        int i = blockIdx.x * 256 + tid;
        if (i >= NN * 64) return;
        int n = i >> 6, c = i & 63;
        float q0 = sQ[c * 2], q1 = sQ[c * 2 + 1];
        const float* xp = x + n * 6;
        float v0 = xp[0] * q0 + xp[3] * q1;
        float v1 = xp[1] * q0 + xp[4] * q1;
        float v2 = xp[2] * q0 + xp[5] * q1;
        int base = n * 192 + c * 3;
        g_yv[0][base + 0] = v0; g_yv[0][base + 1] = v1; g_yv[0][base + 2] = v2;
        g_yv[1][base + 0] = v0; g_yv[1][base + 1] = v1; g_yv[1][base + 2] = v2;
        g_ys[0][i] = 0.f; g_ys[1][i] = 0.f;
        if (c < 3) g_pos[n * 3 + c] = xp[c];
        reinterpret_cast<float4*>(g_agg)[i] = make_float4(0.f, 0.f, 0.f, 0.f);
        int d = c;
        float r0 = sR[d], r1 = sR[64 + d];
#pragma unroll
        for (int xx = 0; xx < 3; xx++)
            g_v1[n * 192 + xx * 64 + d] = xp[xx] * r0 + xp[3 + xx] * r1;
    } else if (blockIdx.x < 5256) {
        // ---- B precompute, tiled (writes dup-bf16x2) ----
        int b = blockIdx.x - 5000;
        __shared__ __align__(16) float semb[3200];
        for (int i = tid; i < 3200; i += 256) semb[i] = emb[i];
        __syncthreads();
        if (b < 128) {
            int l = b >> 6, c = b & 63;
            int o = tid & 127, ah = tid >> 7;
            float wcol[32];
            const float* w = scs + ((size_t)(l * 64 + c) * 32) * 128 + o;
#pragma unroll
            for (int e2 = 0; e2 < 32; e2++) wcol[e2] = w[e2 * 128];
            int a0 = ah * 50, a1 = a0 + 50;
            for (int a = a0; a < a1; a++) {
                const float4* em = (const float4*)(semb + a * 32);
                float acc = 0.f;
#pragma unroll
                for (int e4 = 0; e4 < 8; e4++) {
                    float4 u = em[e4];
                    acc += u.x * wcol[e4 * 4] + u.y * wcol[e4 * 4 + 1] +
                           u.z * wcol[e4 * 4 + 2] + u.w * wcol[e4 * 4 + 3];
                }
                g_Bsd[((size_t)(l * 100 + a) * 64 + c) * 128 + o] = dupbf(acc);
            }
        } else {
            int b2 = b - 128;
            int l = b2 >> 6, c = b2 & 63;
            int o = tid & 63, ah = tid >> 6;
            float wcol[32];
            const float* w = scv + ((size_t)(l * 64 + c) * 32) * 64 + o;
#pragma unroll
            for (int e2 = 0; e2 < 32; e2++) wcol[e2] = w[e2 * 64];
            int a0 = ah * 25, a1 = a0 + 25;
            for (int a = a0; a < a1; a++) {
                const float4* em = (const float4*)(semb + a * 32);
                float acc = 0.f;
#pragma unroll
                for (int e4 = 0; e4 < 8; e4++) {
                    float4 u = em[e4];
                    acc += u.x * wcol[e4 * 4] + u.y * wcol[e4 * 4 + 1] +
                           u.z * wcol[e4 * 4 + 2] + u.w * wcol[e4 * 4 + 3];
                }
                g_Bvd[((size_t)(l * 100 + a) * 64 + c) * 64 + o] = dupbf(acc);
            }
        }
    } else if (blockIdx.x == 5256) {
        // single-block node counting sort by attr, segments padded to 8
        __shared__ int scnt[128], soff[128], spos[128];
        if (tid < 128) { scnt[tid] = 0; spos[tid] = 0; }
        __syncthreads();
        for (int n = tid; n < NN; n += 256) atomicAdd(&scnt[attr[n]], 1);
        __syncthreads();
        int pc = 0;
        if (tid < 128) { pc = (scnt[tid] + 7) & ~7; soff[tid] = pc; }
        __syncthreads();
        for (int off = 1; off < 128; off <<= 1) {
            int v = 0;
            if (tid < 128 && tid >= off) v = soff[tid - off];
            __syncthreads();
            if (tid < 128) soff[tid] += v;
            __syncthreads();
        }
        if (tid < 128) soff[tid] -= pc;
        __syncthreads();
        for (int i = tid; i < NPAD; i += 256) g_nidx[i] = -1;
        __syncthreads();
        for (int n = tid; n < NN; n += 256) {
            int a = attr[n];
            int p = soff[a] + atomicAdd(&spos[a], 1);
            g_nidx[p] = n;
            g_nattr[p] = a;
        }
    } else if (blockIdx.x < 5273) {
        // weight conversion to dup-bf16x2 (16 blocks)
        const int T1 = NL * 8192, T2 = T1 + NL * 4096, T3 = T2 + NL * 4096, T4 = T3 + NL * 4096;
        for (int i = (blockIdx.x - 5257) * 256 + tid; i < T4; i += 16 * 256) {
            if (i < T1) g_wL2s[i] = dupbf(lin2s[i]);
            else if (i < T2) g_wL2v[i - T1] = dupbf(lin2v[i - T1]);
            else if (i < T3) g_wSs[i - T2] = dupbf(sis[i - T2]);
            else g_wSv[i - T3] = dupbf(siv[i - T3]);
        }
    } else {
        // FILTERED edge histogram (layer-0 positions = x)
        for (int e = (blockIdx.x - 5273) * 256 + tid; e < NE; e += 1280 * 256) {
            int s = esrc[e], d = edst[e];
            float dx = x[s * 6 + 0] - x[d * 6 + 0];
            float dy = x[s * 6 + 1] - x[d * 6 + 1];
            float dz = x[s * 6 + 2] - x[d * 6 + 2];
            if (dx * dx + dy * dy + dz * dz < MAXR * MAXR)
                atomicAdd(&g_ecnt[d], 1);
        }
    }
}

// ---------------- edge offset scan (writes surviving count) ----------------
__global__ void __launch_bounds__(512) k_scan_e() {
    __shared__ int sp[512];
    int t = threadIdx.x;
    const int CH = 40;
    int base = t * CH;
    int part = 0;
    for (int i = 0; i < CH; i++) {
        int idx = base + i;
        if (idx < NN) part += g_ecnt[idx];
    }
    sp[t] = part;
    __syncthreads();
    for (int off = 1; off < 512; off <<= 1) {
        int v = (t >= off) ? sp[t - off] : 0;
        __syncthreads();
        sp[t] += v;
        __syncthreads();
    }
    if (t == 511) g_nesurv = sp[511];
    int run = sp[t] - part;
    for (int i = 0; i < CH; i++) {
        int idx = base + i;
        if (idx < NN) { g_eoff[idx] = run; run += g_ecnt[idx]; }
    }
}

// ---------------- filtered edge scatter ----------------
__global__ void k_scat_e(const int* __restrict__ esrc, const int* __restrict__ edst,
                         const float* __restrict__ x) {
    for (int e = blockIdx.x * 256 + threadIdx.x; e < NE; e += 1280 * 256) {
        int s = esrc[e], d = edst[e];
        float dx = x[s * 6 + 0] - x[d * 6 + 0];
        float dy = x[s * 6 + 1] - x[d * 6 + 1];
        float dz = x[s * 6 + 2] - x[d * 6 + 2];
        if (dx * dx + dy * dy + dz * dz < MAXR * MAXR) {
            int p = g_eoff[d] + atomicAdd(&g_eppos[d], 1);
            g_ssrc[p] = s;
            g_sdst[p] = d;
        }
    }
}

// ------- pre (layer 1) + sort-counter cleanup for next call's hist -------
__global__ void __launch_bounds__(256) k_pre(const float* __restrict__ lin1s,
                                             const float* __restrict__ lin1v,
                                             int layer, int cur) {
    __shared__ float sWs[4096], sWv[4096];
    __shared__ float sy[8][256];
    int tid = threadIdx.x;
    {
        int i = blockIdx.x * 256 + tid;
        if (i < NN) { g_ecnt[i] = 0; g_eppos[i] = 0; }
    }
    const float* Ws = lin1s + layer * 4096;
    const float* Wv = lin1v + layer * 4096;
    for (int k = tid; k < 4096; k += 256) { sWs[k] = Ws[k]; sWv[k] = Wv[k]; }
    const float* ys = g_ys[cur];
    const float* yv = g_yv[cur];
    int n0 = blockIdx.x * 8;
    for (int k = tid; k < 2048; k += 256) {
        int nn = k >> 8, j = k & 255;
        int n = n0 + nn;
        sy[nn][j] = (j < 64) ? ys[n * 64 + j] : yv[n * 192 + j - 64];
    }
    __syncthreads();
    for (int nn = 0; nn < 8; nn++) {
        int n = n0 + nn;
        if (tid < 64) {
            int d = tid;
            float acc = 0.f;
#pragma unroll 8
            for (int c = 0; c < 64; c++) acc += sy[nn][c] * sWs[c * 64 + d];
            g_s1[n * 64 + d] = acc;
        } else {
            int idx = tid - 64;
            int d = idx & 63, xx = idx >> 6;
            float acc = 0.f;
#pragma unroll 8
            for (int c = 0; c < 64; c++) acc += sy[nn][64 + c * 3 + xx] * sWv[c * 64 + d];
            g_v1[n * 192 + xx * 64 + d] = acc;
        }
    }
}

// -------- per-edge scalar math (W1 in regs); cut = sin^2(th) identity --------
__device__ __forceinline__ float edge_scalar(float ev0, float ev1, float ev2, float l2,
                                             const float* w1r, float br,
                                             float& ea0, float& ea1, float& ea2) {
    const float PI = 3.14159265358979f;
    float elen = sqrtf(l2);
    float safe = fmaxf(elen, 1e-9f);
    float inv = 1.0f / safe;
    float th = (PI / MAXR) * safe;
    float sk = __sinf(th), c2 = 2.f * __cosf(th);
    float ca = sk * sk * 1.7320508075688772f * inv;
    ea0 = ca * ev0; ea1 = ca * ev1; ea2 = ca * ev2;
    float skm1 = 0.f, skk = sk;
    float fac = 2.5298221281347035f * inv;
    float hs = br;
#pragma unroll
    for (int k = 0; k < 8; k++) {
        hs += (fac * skk) * w1r[k];
        float t = c2 * skk - skm1; skm1 = skk; skk = t;
    }
    return hs / (1.f + __expf(-hs));  // silu
}

// W2 duplicated-bf16x2 layout: sW2d[k*32+lane] = {dup(w0),dup(w1),dup(w2),dup(w3)}
__device__ __forceinline__ void fill_w2d(uint4* sW2d, const float* rW2, int layer,
                                         int tid) {
    for (int t = tid; t < 1024; t += 256) {
        int k = t >> 5, ln = t & 31;
        const float* base = rW2 + layer * 4096 + k * 128;
        uint4 v;
        v.x = dupbf(base[ln]);
        v.y = dupbf(base[32 + ln]);
        v.z = dupbf(base[64 + ln]);
        v.w = dupbf(base[96 + ln]);
        sW2d[t] = v;
    }
}

// -------- edge: dst-sorted filtered list, 4-edge groups; SKIP=1 drops s1 path --------
template <int SKIP>
__global__ void __launch_bounds__(256) k_edge(const float* __restrict__ rW1,
                                              const float* __restrict__ rb1,
                                              const float* __restrict__ rW2,
                                              int layer) {
    __shared__ uint4 sW2d[1024];   // 16 KB
    int tid = threadIdx.x;
    int lane = tid & 31;
    fill_w2d(sW2d, rW2, layer, tid);
    float w1r[8];
#pragma unroll
    for (int k = 0; k < 8; k++) w1r[k] = rW1[layer * 256 + k * 32 + lane];
    float br = rb1[layer * 32 + lane];
    __syncthreads();
    int cnt = g_nesurv;
    int warp = (blockIdx.x * 256 + tid) >> 5;
    int nw = gridDim.x * 8;
    int K = (cnt + nw - 1) / nw;
    int e0 = warp * K;
    if (e0 >= cnt) return;
    int e1 = e0 + K; if (e1 > cnt) e1 = cnt;
    float4 acc0 = make_float4(0.f, 0.f, 0.f, 0.f);
    float4 acc1 = make_float4(0.f, 0.f, 0.f, 0.f);
    bool touched = false;
    int cur = -1;
    __nv_bfloat162 zz; zz.x = __float2bfloat16(0.f); zz.y = zz.x;
    for (int e = e0; e < e1; e += 4) {
        int cnt4 = e1 - e; if (cnt4 > 4) cnt4 = 4;
        int srcs[4], dsts[4];
        float hv4[4], eaX[4], eaY[4], eaZ[4];
#pragma unroll
        for (int i = 0; i < 4; i++) {
            int idx = (i < cnt4) ? (e + i) : (e + cnt4 - 1);
            int d = g_sdst[idx], s = g_ssrc[idx];
            srcs[i] = s; dsts[i] = d;
            float dp0 = g_pos[d * 3 + 0], dp1 = g_pos[d * 3 + 1], dp2 = g_pos[d * 3 + 2];
            float ev0 = g_pos[s * 3 + 0] - dp0;
            float ev1 = g_pos[s * 3 + 1] - dp1;
            float ev2 = g_pos[s * 3 + 2] - dp2;
            float l2 = ev0 * ev0 + ev1 * ev1 + ev2 * ev2;
            float h = edge_scalar(ev0, ev1, ev2, l2, w1r, br, eaX[i], eaY[i], eaZ[i]);
            hv4[i] = (i < cnt4) ? h : 0.f;
        }
        __nv_bfloat162 h01 = __floats2bfloat162_rn(hv4[0], hv4[1]);
        __nv_bfloat162 h23 = __floats2bfloat162_rn(hv4[2], hv4[3]);
        unsigned u01 = *reinterpret_cast<unsigned*>(&h01);
        unsigned u23 = *reinterpret_cast<unsigned*>(&h23);
        __nv_bfloat162 p0 = zz, p1 = zz, p2 = zz, p3 = zz;
        __nv_bfloat162 q0 = zz, q1 = zz, q2 = zz, q3 = zz;
#pragma unroll
        for (int k = 0; k < 32; k++) {
            unsigned s01 = __shfl_sync(0xffffffffu, u01, k);
            unsigned s23 = __shfl_sync(0xffffffffu, u23, k);
            __nv_bfloat162 b01 = asbf2(s01);
            __nv_bfloat162 b23 = asbf2(s23);
            if (SKIP) {
                // only w2/w3 needed: LDS.64 of the upper half
                uint2 wv2 = *reinterpret_cast<const uint2*>(
                    reinterpret_cast<const char*>(&sW2d[k * 32 + lane]) + 8);
                p2 = __hfma2(b01, asbf2(wv2.x), p2);
                p3 = __hfma2(b01, asbf2(wv2.y), p3);
                q2 = __hfma2(b23, asbf2(wv2.x), q2);
                q3 = __hfma2(b23, asbf2(wv2.y), q3);
            } else {
                uint4 wv = sW2d[k * 32 + lane];
                p0 = __hfma2(b01, asbf2(wv.x), p0);
                p1 = __hfma2(b01, asbf2(wv.y), p1);
                p2 = __hfma2(b01, asbf2(wv.z), p2);
                p3 = __hfma2(b01, asbf2(wv.w), p3);
                q0 = __hfma2(b23, asbf2(wv.x), q0);
                q1 = __hfma2(b23, asbf2(wv.y), q1);
                q2 = __hfma2(b23, asbf2(wv.z), q2);
                q3 = __hfma2(b23, asbf2(wv.w), q3);
            }
        }
        float2 f0p = __bfloat1622float2(p0), f1p = __bfloat1622float2(p1);
        float2 f2p = __bfloat1622float2(p2), f3p = __bfloat1622float2(p3);
        float2 f0q = __bfloat1622float2(q0), f1q = __bfloat1622float2(q1);
        float2 f2q = __bfloat1622float2(q2), f3q = __bfloat1622float2(q3);
        float w0v[4] = {f0p.x, f0p.y, f0q.x, f0q.y};
        float w1v[4] = {f1p.x, f1p.y, f1q.x, f1q.y};
        float w2v[4] = {f2p.x, f2p.y, f2q.x, f2q.y};
        float w3v[4] = {f3p.x, f3p.y, f3q.x, f3q.y};
#pragma unroll
        for (int i = 0; i < 4; i++) {
            int dst = dsts[i];
            if (dst != cur) {
                if (touched) {
                    float4* ap = reinterpret_cast<float4*>(g_agg + (size_t)cur * 256);
                    atomicAdd(ap + lane, acc0);
                    atomicAdd(ap + lane + 32, acc1);
                    acc0 = make_float4(0.f, 0.f, 0.f, 0.f);
                    acc1 = make_float4(0.f, 0.f, 0.f, 0.f);
                    touched = false;
                }
                cur = dst;
            }
            int src = srcs[i];
            float ex = eaX[i], ey = eaY[i], ez = eaZ[i];
            if (!SKIP) {
                const float* s1p = g_s1 + (size_t)src * 64;
                float sa = s1p[lane] * w0v[i];
                float sb = s1p[lane + 32] * w1v[i];
                acc0.x += sa * ex; acc0.y += sa * ey; acc0.z += sa * ez;
                acc1.x += sb * ex; acc1.y += sb * ey; acc1.z += sb * ez;
            }
            const float* v1p = g_v1 + (size_t)src * 192;
            float da = w2v[i] * (v1p[lane] * ex + v1p[64 + lane] * ey + v1p[128 + lane] * ez);
            float db = w3v[i] * (v1p[lane + 32] * ex + v1p[96 + lane] * ey + v1p[160 + lane] * ez);
            acc0.w += da;
            acc1.w += db;
            touched = true;
        }
    }
    if (touched) {
        float4* ap = reinterpret_cast<float4*>(g_agg + (size_t)cur * 256);
        atomicAdd(ap + lane, acc0);
        atomicAdd(ap + lane + 32, acc1);
    }
}

// ------ post: node-pair bf16x2 HFMA2 matvec; L0=1 drops zero-input chains ------
template <int L0>
__global__ void __launch_bounds__(256, 4) k_post(const float* __restrict__ hv,
                                                 const float* __restrict__ mv,
                                                 int layer, int cur,
                                                 float* __restrict__ outp) {
    __shared__ float s_Q[128];
    __shared__ __align__(16) float s_ys[8][64], s_aggs[8][64];
    __shared__ __align__(16) float s_yv[8][192], s_aggv[8][192];   // [xx*64+c]
    __shared__ __align__(16) unsigned sPa[256], sPy[256];          // [c*4+p]
    __shared__ __align__(16) unsigned sPav[768], sPyv[768];        // [(xx*64+c)*4+p]
    __shared__ __align__(16) unsigned s_outs_p[512];
    __shared__ __align__(16) unsigned s_y2s_p[256];
    __shared__ __align__(16) unsigned s_outv_p[768];
    __shared__ __align__(16) unsigned s_y2v_p[768];
    __shared__ float s_newv[8][192];
    int tid = threadIdx.x;
    if (tid < 128) s_Q[tid] = g_Q[tid];
    float hh = hv[layer] * hv[layer];
    float m = mv[layer];
    float* ys_new = g_ys[cur ^ 1];
    float* yv_new = g_yv[cur ^ 1];
    const float* ys_cur = g_ys[cur];
    const float* yv_cur = g_yv[cur];
    __nv_bfloat162 zz; zz.x = __float2bfloat16(0.f); zz.y = zz.x;
    for (int it = 0; it < 2; it++) {
        int pbase = blockIdx.x * 16 + it * 8;
        for (int t = tid; t < 512; t += 256) {
            int node = t >> 6, j = t & 63;
            int n = g_nidx[pbase + node];
            if (n >= 0) {
                s_ys[node][j] = ys_cur[n * 64 + j];
                float4 a4 = ((const float4*)g_agg)[n * 64 + j];
                if (L0)
                    ((float4*)g_agg)[n * 64 + j] = make_float4(0.f, 0.f, 0.f, 0.f);
                s_aggs[node][j] = a4.w * INV_NN;
                s_aggv[node][j] = a4.x * INV_NN;
                s_aggv[node][64 + j] = a4.y * INV_NN;
                s_aggv[node][128 + j] = a4.z * INV_NN;
                const float* yvp = yv_cur + n * 192 + j * 3;
                s_yv[node][j] = yvp[0];
                s_yv[node][64 + j] = yvp[1];
                s_yv[node][128 + j] = yvp[2];
            } else {
                s_ys[node][j] = 0.f; s_aggs[node][j] = 0.f;
                s_aggv[node][j] = 0.f; s_aggv[node][64 + j] = 0.f; s_aggv[node][128 + j] = 0.f;
                s_yv[node][j] = 0.f; s_yv[node][64 + j] = 0.f; s_yv[node][128 + j] = 0.f;
            }
        }
        __syncthreads();
        // ---- pack node pairs to bf16x2 ----
        for (int i = tid; i < 2048; i += 256) {
            if (i < 256) {
                int c = i >> 2, p = i & 3;
                __nv_bfloat162 pk = __floats2bfloat162_rn(s_aggs[2 * p][c], s_aggs[2 * p + 1][c]);
                sPa[i] = *reinterpret_cast<unsigned*>(&pk);
            } else if (i < 512) {
                int r = i - 256, c = r >> 2, p = r & 3;
                __nv_bfloat162 pk = __floats2bfloat162_rn(s_ys[2 * p][c], s_ys[2 * p + 1][c]);
                sPy[r] = *reinterpret_cast<unsigned*>(&pk);
            } else if (i < 1280) {
                int r = i - 512, cc = r >> 2, p = r & 3;
                __nv_bfloat162 pk = __floats2bfloat162_rn(s_aggv[2 * p][cc], s_aggv[2 * p + 1][cc]);
                sPav[r] = *reinterpret_cast<unsigned*>(&pk);
            } else {
                int r = i - 1280, cc = r >> 2, p = r & 3;
                __nv_bfloat162 pk = __floats2bfloat162_rn(s_yv[2 * p][cc], s_yv[2 * p + 1][cc]);
                sPyv[r] = *reinterpret_cast<unsigned*>(&pk);
            }
        }
        __syncthreads();
        int a = g_nattr[pbase];
        if (tid < 64) {
            int j2 = tid;
            const uint2* wp = (const uint2*)(g_wL2s + layer * 8192) + j2;
            const uint2* bp = (const uint2*)(g_Bsd + (size_t)(layer * 100 + a) * 8192) + j2;
            bool doY = (j2 < 32);
            const uint2* sp = (const uint2*)(g_wSs + layer * 4096) + j2;
            __nv_bfloat162 aA0[4], aA1[4], aY0[4], aY1[4];
#pragma unroll
            for (int p = 0; p < 4; p++) { aA0[p] = zz; aA1[p] = zz; aY0[p] = zz; aY1[p] = zz; }
            for (int c = 0; c < 64; c++) {
                uint4 A = ((const uint4*)sPa)[c];
                uint2 w = __ldg(wp + c * 64);
                __nv_bfloat162 wx = asbf2(w.x), wy = asbf2(w.y);
                __nv_bfloat162 Ab[4] = {asbf2(A.x), asbf2(A.y), asbf2(A.z), asbf2(A.w)};
#pragma unroll
                for (int p = 0; p < 4; p++) {
                    aA0[p] = __hfma2(wx, Ab[p], aA0[p]);
                    aA1[p] = __hfma2(wy, Ab[p], aA1[p]);
                }
                if (!L0) {
                    uint4 Y = ((const uint4*)sPy)[c];
                    uint2 b = __ldg(bp + c * 64);
                    __nv_bfloat162 bx = asbf2(b.x), by = asbf2(b.y);
                    __nv_bfloat162 Yb[4] = {asbf2(Y.x), asbf2(Y.y), asbf2(Y.z), asbf2(Y.w)};
#pragma unroll
                    for (int p = 0; p < 4; p++) {
                        aA0[p] = __hfma2(bx, Yb[p], aA0[p]);
                        aA1[p] = __hfma2(by, Yb[p], aA1[p]);
                    }
                    if (doY) {
                        uint2 s = __ldg(sp + c * 32);
                        __nv_bfloat162 sx = asbf2(s.x), sy2 = asbf2(s.y);
#pragma unroll
                        for (int p = 0; p < 4; p++) {
                            aY0[p] = __hfma2(sx, Yb[p], aY0[p]);
                            aY1[p] = __hfma2(sy2, Yb[p], aY1[p]);
                        }
                    }
                }
            }
#pragma unroll
            for (int p = 0; p < 4; p++) {
                s_outs_p[(2 * j2 + 0) * 4 + p] = *reinterpret_cast<unsigned*>(&aA0[p]);
                s_outs_p[(2 * j2 + 1) * 4 + p] = *reinterpret_cast<unsigned*>(&aA1[p]);
            }
            if (doY) {
#pragma unroll
                for (int p = 0; p < 4; p++) {
                    s_y2s_p[(2 * j2 + 0) * 4 + p] = *reinterpret_cast<unsigned*>(&aY0[p]);
                    s_y2s_p[(2 * j2 + 1) * 4 + p] = *reinterpret_cast<unsigned*>(&aY1[p]);
                }
            }
        } else if (tid < 160) {
            int id = tid - 64, xx = id >> 5, j2 = id & 31;
            const uint2* wp = (const uint2*)(g_wL2v + layer * 4096) + j2;
            const uint2* bp = (const uint2*)(g_Bvd + (size_t)(layer * 100 + a) * 4096) + j2;
            __nv_bfloat162 a0[4], a1[4];
#pragma unroll
            for (int p = 0; p < 4; p++) { a0[p] = zz; a1[p] = zz; }
            for (int c = 0; c < 64; c++) {
                uint4 Y = ((const uint4*)sPyv)[xx * 64 + c];
                uint2 b = __ldg(bp + c * 32);
                __nv_bfloat162 bx = asbf2(b.x), by = asbf2(b.y);
                __nv_bfloat162 Yb[4] = {asbf2(Y.x), asbf2(Y.y), asbf2(Y.z), asbf2(Y.w)};
#pragma unroll
                for (int p = 0; p < 4; p++) {
                    a0[p] = __hfma2(bx, Yb[p], a0[p]);
                    a1[p] = __hfma2(by, Yb[p], a1[p]);
                }
                if (!L0) {
                    uint4 A = ((const uint4*)sPav)[xx * 64 + c];
                    uint2 w = __ldg(wp + c * 32);
                    __nv_bfloat162 wx = asbf2(w.x), wy = asbf2(w.y);
                    __nv_bfloat162 Ab[4] = {asbf2(A.x), asbf2(A.y), asbf2(A.z), asbf2(A.w)};
#pragma unroll
                    for (int p = 0; p < 4; p++) {
                        a0[p] = __hfma2(wx, Ab[p], a0[p]);
                        a1[p] = __hfma2(wy, Ab[p], a1[p]);
                    }
                }
            }
#pragma unroll
            for (int p = 0; p < 4; p++) {
                s_outv_p[(xx * 64 + 2 * j2 + 0) * 4 + p] = *reinterpret_cast<unsigned*>(&a0[p]);
                s_outv_p[(xx * 64 + 2 * j2 + 1) * 4 + p] = *reinterpret_cast<unsigned*>(&a1[p]);
            }
        } else {
            int id = tid - 160, xx = id / 32, j2 = id % 32;
            const uint2* sp = (const uint2*)(g_wSv + layer * 4096) + j2;
            __nv_bfloat162 a0[4], a1[4];
#pragma unroll
            for (int p = 0; p < 4; p++) { a0[p] = zz; a1[p] = zz; }
            for (int c = 0; c < 64; c++) {
                uint4 Y = ((const uint4*)sPyv)[xx * 64 + c];
                uint2 s = __ldg(sp + c * 32);
                __nv_bfloat162 sx = asbf2(s.x), sy2 = asbf2(s.y);
                __nv_bfloat162 Yb[4] = {asbf2(Y.x), asbf2(Y.y), asbf2(Y.z), asbf2(Y.w)};
#pragma unroll
                for (int p = 0; p < 4; p++) {
                    a0[p] = __hfma2(sx, Yb[p], a0[p]);
                    a1[p] = __hfma2(sy2, Yb[p], a1[p]);
                }
            }
#pragma unroll
            for (int p = 0; p < 4; p++) {
                s_y2v_p[(xx * 64 + 2 * j2 + 0) * 4 + p] = *reinterpret_cast<unsigned*>(&a0[p]);
                s_y2v_p[(xx * 64 + 2 * j2 + 1) * 4 + p] = *reinterpret_cast<unsigned*>(&a1[p]);
            }
        }
        __syncthreads();
        // ---- state update ----
        for (int t = tid; t < 512; t += 256) {
            int node = t >> 6, c = t & 63;
            int n = g_nidx[pbase + node];
            if (n >= 0) {
                int p = node >> 1, hi = node & 1;
                float2 vos = __bfloat1622float2(asbf2(s_outs_p[c * 4 + p]));
                float2 vgt = __bfloat1622float2(asbf2(s_outs_p[(64 + c) * 4 + p]));
                float os = hi ? vos.y : vos.x;
                float gt = hi ? vgt.y : vgt.x;
                float y2 = 0.f;
                if (!L0) {
                    float2 vy2 = __bfloat1622float2(asbf2(s_y2s_p[c * 4 + p]));
                    y2 = hi ? vy2.y : vy2.x;
                }
                float gs = os / (1.f + __expf(-os));
                float gate = 1.f / (1.f + __expf(-gt));
                float yo = ys_new[n * 64 + c];
                float ns = 2.f * s_ys[node][c] - yo + hh * (m * gs + (m - 1.f) * y2);
                ys_new[n * 64 + c] = ns;
#pragma unroll
                for (int xx = 0; xx < 3; xx++) {
                    float2 vov = __bfloat1622float2(asbf2(s_outv_p[(xx * 64 + c) * 4 + p]));
                    float2 vyv = __bfloat1622float2(asbf2(s_y2v_p[(xx * 64 + c) * 4 + p]));
                    float ov = hi ? vov.y : vov.x;
                    float yv2 = hi ? vyv.y : vyv.x;
                    float yov = yv_new[n * 192 + c * 3 + xx];
                    float nv = 2.f * s_yv[node][xx * 64 + c] - yov +
                               hh * (m * gate * ov + (m - 1.f) * yv2);
                    yv_new[n * 192 + c * 3 + xx] = nv;
                    s_newv[node][xx * 64 + c] = nv;
                }
            }
        }
        __syncthreads();
        // ---- projection ----
        if (tid < 48) {
            int node = tid / 6, r = tid % 6, k = r / 3, xx = r % 3;
            int n = g_nidx[pbase + node];
            if (n >= 0) {
                float acc = 0.f;
#pragma unroll 8
                for (int c = 0; c < 64; c++) acc += s_newv[node][xx * 64 + c] * s_Q[c * 2 + k];
                if (L0) {
                    if (k == 0) g_pos[n * 3 + xx] = acc;
                } else {
                    outp[n * 6 + k * 3 + xx] = acc;
                }
            }
        }
        __syncthreads();
    }
}

// ---------------- launch ----------------
extern "C" void kernel_launch(void* const* d_in, const int* in_sizes, int n_in,
                              void* d_out, int out_size) {
    const float* x        = (const float*)d_in[0];
    const int*   attr     = (const int*)d_in[2];
    const int*   esrc     = (const int*)d_in[3];
    const int*   edst     = (const int*)d_in[4];
    const float* emb      = (const float*)d_in[5];
    const float* uplift   = (const float*)d_in[6];
    const float* h        = (const float*)d_in[7];
    const float* mix      = (const float*)d_in[8];
    const float* rW1      = (const float*)d_in[9];
    const float* rb1      = (const float*)d_in[10];
    const float* rW2      = (const float*)d_in[11];
    const float* lin1s    = (const float*)d_in[12];
    const float* lin1v    = (const float*)d_in[13];
    const float* lin2s    = (const float*)d_in[14];
    const float* lin2v    = (const float*)d_in[15];
    const float* scs      = (const float*)d_in[16];
    const float* scv      = (const float*)d_in[17];
    const float* sis      = (const float*)d_in[18];
    const float* siv      = (const float*)d_in[19];
    float* out = (float*)d_out;

    const int PB = NPAD / 16;  // 1300

    k_init<<<6553, 256>>>(x, uplift, emb, scs, scv, lin1v, lin2s, lin2v, sis, siv,
                          attr, esrc, edst);                                   // 0
    k_scan_e<<<1, 512>>>();                                                    // 1
    k_scat_e<<<1280, 256>>>(esrc, edst, x);                                    // 2
    k_edge<1><<<2000, 256>>>(rW1, rb1, rW2, 0);                                // 3 <- profiled
    k_post<1><<<PB, 256>>>(h, mix, 0, 0, out);                                 // 4
    k_pre<<<NN / 8, 256>>>(lin1s, lin1v, 1, 1);                                // 5 (+cnt cleanup)
    k_edge<0><<<2000, 256>>>(rW1, rb1, rW2, 1);                                // 6
    k_post<0><<<PB, 256>>>(h, mix, 1, 1, out);                                 // 7
}